// round 3
// baseline (speedup 1.0000x reference)
#include <cuda_runtime.h>
#include <cuda_bf16.h>
#include <math.h>

typedef unsigned int u32;
typedef unsigned long long u64;

// Problem constants
#define Bdim 4
#define Sdim 1024
#define Ddim 512
#define Fdim 2048
#define Hdim 8
#define Edim 8
#define HD 64
#define NTOK 4096        // B*S
#define CAPMAX 256
#define QKVW 1536        // 3*D

// ---------------- scratch (device globals; no allocation) ----------------
__device__ float g_qkv [NTOK * QKVW];
__device__ float g_attn[NTOK * Ddim];
__device__ float g_aout[NTOK * Ddim];
__device__ float g_h   [NTOK * Ddim];
__device__ float g_moe [NTOK * Ddim];
__device__ float g_hg  [32 * CAPMAX * Ddim];          // gathered tokens fp32
__device__ float g_yg  [32 * CAPMAX * Fdim];          // FFN1 out fp32
__device__ __nv_bfloat16 g_w1h[Edim * Fdim * Ddim];   // wi^T  [e][f][d] hi
__device__ __nv_bfloat16 g_w1l[Edim * Fdim * Ddim];
__device__ __nv_bfloat16 g_w2h[Edim * Ddim * Fdim];   // wo^T  [e][d][f] hi
__device__ __nv_bfloat16 g_w2l[Edim * Ddim * Fdim];
__device__ int   g_idx [NTOK];
__device__ float g_pmax[NTOK];
__device__ int   g_etok[32 * CAPMAX];
__device__ float g_escale[32 * CAPMAX];
__device__ int   g_count[32];

// ---------------- small helpers ----------------
__device__ __forceinline__ u32 smem_u32(const void* p) {
    u32 a;
    asm("{ .reg .u64 t; cvta.to.shared.u64 t, %1; cvt.u32.u64 %0, t; }" : "=r"(a) : "l"(p));
    return a;
}
__device__ __forceinline__ u32 bfpack(__nv_bfloat16 a, __nv_bfloat16 b) {
    __nv_bfloat162 t;
    t.x = a; t.y = b;
    return *(u32*)&t;
}
__device__ __forceinline__ void ldm4(u32 r[4], u32 addr) {
    asm volatile("ldmatrix.sync.aligned.m8n8.x4.shared.b16 {%0,%1,%2,%3}, [%4];"
                 : "=r"(r[0]), "=r"(r[1]), "=r"(r[2]), "=r"(r[3]) : "r"(addr));
}
__device__ __forceinline__ void mma16816(float c[4], const u32 a[4], const u32 b[2]) {
    asm volatile(
        "mma.sync.aligned.m16n8k16.row.col.f32.bf16.bf16.f32 "
        "{%0,%1,%2,%3}, {%4,%5,%6,%7}, {%8,%9}, {%0,%1,%2,%3};"
        : "+f"(c[0]), "+f"(c[1]), "+f"(c[2]), "+f"(c[3])
        : "r"(a[0]), "r"(a[1]), "r"(a[2]), "r"(a[3]), "r"(b[0]), "r"(b[1]));
}
__device__ __forceinline__ float gelu_exact(float x) {
    return 0.5f * x * (1.0f + erff(x * 0.70710678118654752f));
}

// ---------------- HMMA bf16-split NT mainloop ----------------
// Block tile 128x128, 256 threads (8 warps, 4M x 2N), warp tile 32x64.
// A: fp32 [128 rows x K] (row stride LDA), split to bf16 hi/lo on smem store.
// B: pre-split bf16 hi/lo [128 rows(N) x K] (row stride LDB).
// C = A@B^T in c[2][8][4] fragments (3-pass precision split).
template<int LDA, int LDB, int KTOT>
__device__ __forceinline__ void hmma_nt(
    const float* __restrict__ A,
    const __nv_bfloat16* __restrict__ Bh, const __nv_bfloat16* __restrict__ Bl,
    float (&c)[2][8][4])
{
    __shared__ __align__(16) char Ash[128 * 80];
    __shared__ __align__(16) char Asl[128 * 80];
    __shared__ __align__(16) char Bsh[128 * 80];
    __shared__ __align__(16) char Bsl[128 * 80];

    const int tid = threadIdx.x;
    const int lane = tid & 31, wid = tid >> 5;
    const int wm = (wid & 3) * 32, wn = (wid >> 2) * 64;
    const u32 a_base  = smem_u32(Ash);
    const u32 al_base = smem_u32(Asl);
    const u32 b_base  = smem_u32(Bsh);
    const u32 bl_base = smem_u32(Bsl);
    const int rowA = (lane & 7) + ((lane >> 3) & 1) * 8;
    const int colA = (lane >> 4) * 16;
    const int rowB = (lane & 7) + (lane >> 4) * 8;
    const int colB = ((lane >> 3) & 1) * 16;

#pragma unroll
    for (int i = 0; i < 2; i++)
#pragma unroll
        for (int j = 0; j < 8; j++)
#pragma unroll
            for (int q = 0; q < 4; q++) c[i][j][q] = 0.0f;

    for (int k0 = 0; k0 < KTOT; k0 += 32) {
        __syncthreads();
        // A: 128 rows x 32 fp32 -> bf16 hi/lo
#pragma unroll
        for (int i = 0; i < 4; i++) {
            int t = tid + i * 256;
            int r = t >> 3, kq = t & 7;
            float4 v = *(const float4*)(A + (size_t)r * LDA + k0 + kq * 4);
            __nv_bfloat16 h0 = __float2bfloat16(v.x);
            __nv_bfloat16 h1 = __float2bfloat16(v.y);
            __nv_bfloat16 h2 = __float2bfloat16(v.z);
            __nv_bfloat16 h3 = __float2bfloat16(v.w);
            __nv_bfloat16 l0 = __float2bfloat16(v.x - __bfloat162float(h0));
            __nv_bfloat16 l1 = __float2bfloat16(v.y - __bfloat162float(h1));
            __nv_bfloat16 l2 = __float2bfloat16(v.z - __bfloat162float(h2));
            __nv_bfloat16 l3 = __float2bfloat16(v.w - __bfloat162float(h3));
            u32 off = r * 80 + kq * 8;
            ((u32*)(Ash + off))[0] = bfpack(h0, h1);
            ((u32*)(Ash + off))[1] = bfpack(h2, h3);
            ((u32*)(Asl + off))[0] = bfpack(l0, l1);
            ((u32*)(Asl + off))[1] = bfpack(l2, l3);
        }
        // B: 128 rows x 32 bf16 hi/lo
#pragma unroll
        for (int i = 0; i < 2; i++) {
            int t = tid + i * 256;
            int r = t >> 2, kq = t & 3;
            *(uint4*)(Bsh + r * 80 + kq * 16) = *(const uint4*)(Bh + (size_t)r * LDB + k0 + kq * 8);
            *(uint4*)(Bsl + r * 80 + kq * 16) = *(const uint4*)(Bl + (size_t)r * LDB + k0 + kq * 8);
        }
        __syncthreads();
#pragma unroll
        for (int kk = 0; kk < 32; kk += 16) {
            u32 ah[2][4], al2[2][4], bhf[8][2], blf[8][2];
#pragma unroll
            for (int s = 0; s < 2; s++) {
                ldm4(ah[s],  a_base  + (wm + s * 16 + rowA) * 80 + kk * 2 + colA);
                ldm4(al2[s], al_base + (wm + s * 16 + rowA) * 80 + kk * 2 + colA);
            }
#pragma unroll
            for (int p = 0; p < 4; p++) {
                u32 t4[4];
                ldm4(t4, b_base + (wn + p * 16 + rowB) * 80 + kk * 2 + colB);
                bhf[2 * p][0] = t4[0]; bhf[2 * p][1] = t4[1];
                bhf[2 * p + 1][0] = t4[2]; bhf[2 * p + 1][1] = t4[3];
                ldm4(t4, bl_base + (wn + p * 16 + rowB) * 80 + kk * 2 + colB);
                blf[2 * p][0] = t4[0]; blf[2 * p][1] = t4[1];
                blf[2 * p + 1][0] = t4[2]; blf[2 * p + 1][1] = t4[3];
            }
#pragma unroll
            for (int i2 = 0; i2 < 2; i2++)
#pragma unroll
                for (int j = 0; j < 8; j++) {
                    mma16816(c[i2][j], ah[i2],  bhf[j]);
                    mma16816(c[i2][j], ah[i2],  blf[j]);
                    mma16816(c[i2][j], al2[i2], bhf[j]);
                }
        }
    }
}

// ---------------- generic zero ----------------
__global__ void zero_kernel(float* __restrict__ p, int n) {
    int i = blockIdx.x * blockDim.x + threadIdx.x;
    if (i < n) p[i] = 0.0f;
}

// ---------------- weight transpose + bf16 split: src[m][R][C] -> dst[m][C][R] ----------------
__global__ void __launch_bounds__(256) transpose_split_kernel(
    const float* __restrict__ src, __nv_bfloat16* __restrict__ dh,
    __nv_bfloat16* __restrict__ dl, int R, int C)
{
    __shared__ float t[32][33];
    const int m = blockIdx.z;
    const int c0 = blockIdx.x * 32, r0 = blockIdx.y * 32;
    const int tx = threadIdx.x & 31, ty = threadIdx.x >> 5;
    const float* s = src + (size_t)m * R * C;
#pragma unroll
    for (int j = 0; j < 32; j += 8)
        t[ty + j][tx] = s[(size_t)(r0 + ty + j) * C + c0 + tx];
    __syncthreads();
    const size_t obase = (size_t)m * R * C;
#pragma unroll
    for (int j = 0; j < 32; j += 8) {
        float v = t[tx][ty + j];
        __nv_bfloat16 h = __float2bfloat16(v);
        __nv_bfloat16 l = __float2bfloat16(v - __bfloat162float(h));
        dh[obase + (size_t)(c0 + ty + j) * R + r0 + tx] = h;
        dl[obase + (size_t)(c0 + ty + j) * R + r0 + tx] = l;
    }
}

// ---------------- GEMM NT + bias (fp32 FFMA): C[M,N] = A[M,K] @ B[N,K]^T + bias ----------------
__global__ void __launch_bounds__(256) gemm_nt_bias_kernel(
    const float* __restrict__ A, const float* __restrict__ Bm,
    const float* __restrict__ bias, float* __restrict__ C,
    int M, int N, int K)
{
    __shared__ float As[8][128];
    __shared__ float Bs[8][128];
    const int bm = blockIdx.y * 128;
    const int bn = blockIdx.x * 128;
    const int tid = threadIdx.x;
    const int tx = tid & 15, ty = tid >> 4;
    const int lr = tid >> 1;
    const int lk = (tid & 1) * 4;
    const float* Aptr = A + (size_t)(bm + lr) * K + lk;
    const float* Bptr = Bm + (size_t)(bn + lr) * K + lk;

    float acc[8][8];
#pragma unroll
    for (int i = 0; i < 8; i++)
#pragma unroll
        for (int j = 0; j < 8; j++) acc[i][j] = 0.0f;

    for (int k0 = 0; k0 < K; k0 += 8) {
        float4 av = *(const float4*)(Aptr + k0);
        float4 bv = *(const float4*)(Bptr + k0);
        As[lk + 0][lr] = av.x; As[lk + 1][lr] = av.y;
        As[lk + 2][lr] = av.z; As[lk + 3][lr] = av.w;
        Bs[lk + 0][lr] = bv.x; Bs[lk + 1][lr] = bv.y;
        Bs[lk + 2][lr] = bv.z; Bs[lk + 3][lr] = bv.w;
        __syncthreads();
#pragma unroll
        for (int kk = 0; kk < 8; kk++) {
            float a[8], b[8];
#pragma unroll
            for (int i = 0; i < 8; i++) a[i] = As[kk][ty * 8 + i];
#pragma unroll
            for (int j = 0; j < 8; j++) b[j] = Bs[kk][tx * 8 + j];
#pragma unroll
            for (int i = 0; i < 8; i++)
#pragma unroll
                for (int j = 0; j < 8; j++)
                    acc[i][j] = fmaf(a[i], b[j], acc[i][j]);
        }
        __syncthreads();
    }
#pragma unroll
    for (int i = 0; i < 8; i++) {
        int row = bm + ty * 8 + i;
        float* cp = C + (size_t)row * N + bn + tx * 8;
#pragma unroll
        for (int j = 0; j < 8; j++) cp[j] = acc[i][j] + bias[bn + tx * 8 + j];
    }
}

// ---------------- flash attention (fp32, hd=64) ----------------
#define FA_SMEM_FLOATS (3 * 64 * 65 + 4 * 64 + 3 * 64)
__global__ void __launch_bounds__(256) flash_attn_kernel(
    const float* __restrict__ qkv, float* __restrict__ out)
{
    extern __shared__ float smf[];
    float* Qs   = smf;
    float* KVs  = Qs + 64 * 65;
    float* Ps   = KVs + 64 * 65;
    float* psum = Ps + 64 * 65;
    float* mrow = psum + 256;
    float* lrow = mrow + 64;
    float* arow = lrow + 64;

    const int qt = blockIdx.x, h = blockIdx.y, b = blockIdx.z;
    const int tid = threadIdx.x;
    const int tx = tid & 15, ty = tid >> 4;
    const int q0 = qt * 64;
    const float scale = 0.125f;

    {
        int r = tid >> 2;
        int c0 = (tid & 3) * 16;
        const float* src = qkv + ((size_t)(b * Sdim + q0 + r)) * QKVW + h * HD + c0;
#pragma unroll
        for (int i = 0; i < 4; i++) {
            float4 v = *(const float4*)(src + 4 * i);
            Qs[r * 65 + c0 + 4 * i + 0] = v.x * scale;
            Qs[r * 65 + c0 + 4 * i + 1] = v.y * scale;
            Qs[r * 65 + c0 + 4 * i + 2] = v.z * scale;
            Qs[r * 65 + c0 + 4 * i + 3] = v.w * scale;
        }
    }
    if (tid < 64) { mrow[tid] = -1e30f; lrow[tid] = 0.0f; }

    float acc[4][4];
#pragma unroll
    for (int i = 0; i < 4; i++)
#pragma unroll
        for (int j = 0; j < 4; j++) acc[i][j] = 0.0f;

    for (int kt = 0; kt < 16; kt++) {
        __syncthreads();
        {
            int r = tid >> 2;
            int c0 = (tid & 3) * 16;
            const float* src = qkv + ((size_t)(b * Sdim + kt * 64 + r)) * QKVW + Ddim + h * HD + c0;
#pragma unroll
            for (int i = 0; i < 4; i++) {
                float4 v = *(const float4*)(src + 4 * i);
                KVs[r * 65 + c0 + 4 * i + 0] = v.x;
                KVs[r * 65 + c0 + 4 * i + 1] = v.y;
                KVs[r * 65 + c0 + 4 * i + 2] = v.z;
                KVs[r * 65 + c0 + 4 * i + 3] = v.w;
            }
        }
        __syncthreads();
        float sacc[4][4];
#pragma unroll
        for (int i = 0; i < 4; i++)
#pragma unroll
            for (int j = 0; j < 4; j++) sacc[i][j] = 0.0f;
#pragma unroll 4
        for (int kk = 0; kk < 64; kk++) {
            float qv[4], kv[4];
#pragma unroll
            for (int i = 0; i < 4; i++) qv[i] = Qs[(ty * 4 + i) * 65 + kk];
#pragma unroll
            for (int j = 0; j < 4; j++) kv[j] = KVs[(tx * 4 + j) * 65 + kk];
#pragma unroll
            for (int i = 0; i < 4; i++)
#pragma unroll
                for (int j = 0; j < 4; j++)
                    sacc[i][j] = fmaf(qv[i], kv[j], sacc[i][j]);
        }
#pragma unroll
        for (int i = 0; i < 4; i++)
#pragma unroll
            for (int j = 0; j < 4; j++)
                Ps[(ty * 4 + i) * 65 + tx * 4 + j] = sacc[i][j];
        __syncthreads();
        {
            int r = tid >> 2;
            int c0 = (tid & 3) * 16;
            const float* src = qkv + ((size_t)(b * Sdim + kt * 64 + r)) * QKVW + 2 * Ddim + h * HD + c0;
#pragma unroll
            for (int i = 0; i < 4; i++) {
                float4 v = *(const float4*)(src + 4 * i);
                KVs[r * 65 + c0 + 4 * i + 0] = v.x;
                KVs[r * 65 + c0 + 4 * i + 1] = v.y;
                KVs[r * 65 + c0 + 4 * i + 2] = v.z;
                KVs[r * 65 + c0 + 4 * i + 3] = v.w;
            }
        }
        if (tid < 64) {
            float m = mrow[tid];
#pragma unroll 8
            for (int c = 0; c < 64; c++) m = fmaxf(m, Ps[tid * 65 + c]);
            arow[tid] = __expf(mrow[tid] - m);
            mrow[tid] = m;
        }
        __syncthreads();
        {
            int row = tid & 63, qq = tid >> 6;
            float m = mrow[row];
            float s = 0.0f;
            int c0 = qq * 16;
#pragma unroll
            for (int c = c0; c < c0 + 16; c++) {
                float p = __expf(Ps[row * 65 + c] - m);
                Ps[row * 65 + c] = p;
                s += p;
            }
            psum[qq * 64 + row] = s;
        }
        __syncthreads();
        if (tid < 64)
            lrow[tid] = arow[tid] * lrow[tid] + psum[tid] + psum[64 + tid] + psum[128 + tid] + psum[192 + tid];
        {
            float al[4];
#pragma unroll
            for (int i = 0; i < 4; i++) al[i] = arow[ty * 4 + i];
#pragma unroll
            for (int i = 0; i < 4; i++)
#pragma unroll
                for (int j = 0; j < 4; j++) acc[i][j] *= al[i];
        }
#pragma unroll 4
        for (int kk = 0; kk < 64; kk++) {
            float pv[4], vv[4];
#pragma unroll
            for (int i = 0; i < 4; i++) pv[i] = Ps[(ty * 4 + i) * 65 + kk];
#pragma unroll
            for (int j = 0; j < 4; j++) vv[j] = KVs[kk * 65 + tx * 4 + j];
#pragma unroll
            for (int i = 0; i < 4; i++)
#pragma unroll
                for (int j = 0; j < 4; j++)
                    acc[i][j] = fmaf(pv[i], vv[j], acc[i][j]);
        }
    }
    __syncthreads();
    float inv[4];
#pragma unroll
    for (int i = 0; i < 4; i++) inv[i] = 1.0f / lrow[ty * 4 + i];
#pragma unroll
    for (int i = 0; i < 4; i++) {
        float* op = out + ((size_t)(b * Sdim + q0 + ty * 4 + i)) * Ddim + h * HD + tx * 4;
#pragma unroll
        for (int j = 0; j < 4; j++) op[j] = acc[i][j] * inv[i];
    }
}

// ---------------- fused residual add + LayerNorm ----------------
__global__ void __launch_bounds__(128) add_ln_kernel(
    const float* __restrict__ a, const float* __restrict__ r,
    const float* __restrict__ g, const float* __restrict__ be,
    float* __restrict__ out)
{
    const int n = blockIdx.x;
    const int tid = threadIdx.x;
    __shared__ float red[4], red2[4];
    __shared__ float s_mu, s_rstd;
    const float* ap = a + (size_t)n * Ddim;
    const float* rp = r + (size_t)n * Ddim;
    float v[4];
    float sum = 0.0f, sq = 0.0f;
#pragma unroll
    for (int i = 0; i < 4; i++) {
        v[i] = ap[tid + i * 128] + rp[tid + i * 128];
        sum += v[i];
        sq = fmaf(v[i], v[i], sq);
    }
#pragma unroll
    for (int o = 16; o; o >>= 1) {
        sum += __shfl_xor_sync(0xffffffffu, sum, o);
        sq  += __shfl_xor_sync(0xffffffffu, sq, o);
    }
    if ((tid & 31) == 0) { red[tid >> 5] = sum; red2[tid >> 5] = sq; }
    __syncthreads();
    if (tid == 0) {
        float s = red[0] + red[1] + red[2] + red[3];
        float q = red2[0] + red2[1] + red2[2] + red2[3];
        float mu = s * (1.0f / 512.0f);
        float var = q * (1.0f / 512.0f) - mu * mu;
        s_mu = mu;
        s_rstd = rsqrtf(var + 1e-5f);
    }
    __syncthreads();
    float mu = s_mu, rstd = s_rstd;
#pragma unroll
    for (int i = 0; i < 4; i++) {
        int d = tid + i * 128;
        out[(size_t)n * Ddim + d] = (v[i] - mu) * rstd * g[d] + be[d];
    }
}

// ---------------- router: logits + softmax + argmax ----------------
__global__ void __launch_bounds__(256) router_kernel(
    const float* __restrict__ h, const float* __restrict__ rw,
    float* __restrict__ logits_out)
{
    const int w = threadIdx.x >> 5, l = threadIdx.x & 31;
    const int n = blockIdx.x * 8 + w;
    float acc[8];
#pragma unroll
    for (int e = 0; e < 8; e++) acc[e] = 0.0f;
    const float* hp = h + (size_t)n * Ddim;
    for (int d = l; d < Ddim; d += 32) {
        float hv = hp[d];
        const float4* rp = (const float4*)(rw + d * 8);
        float4 r0 = rp[0], r1 = rp[1];
        acc[0] = fmaf(hv, r0.x, acc[0]); acc[1] = fmaf(hv, r0.y, acc[1]);
        acc[2] = fmaf(hv, r0.z, acc[2]); acc[3] = fmaf(hv, r0.w, acc[3]);
        acc[4] = fmaf(hv, r1.x, acc[4]); acc[5] = fmaf(hv, r1.y, acc[5]);
        acc[6] = fmaf(hv, r1.z, acc[6]); acc[7] = fmaf(hv, r1.w, acc[7]);
    }
#pragma unroll
    for (int e = 0; e < 8; e++)
#pragma unroll
        for (int o = 16; o; o >>= 1)
            acc[e] += __shfl_xor_sync(0xffffffffu, acc[e], o);
    if (l == 0) {
        float m = acc[0]; int arg = 0;
#pragma unroll
        for (int e = 1; e < 8; e++) if (acc[e] > m) { m = acc[e]; arg = e; }
        float s = 0.0f;
#pragma unroll
        for (int e = 0; e < 8; e++) s += __expf(acc[e] - m);
#pragma unroll
        for (int e = 0; e < 8; e++) logits_out[(size_t)n * 8 + e] = acc[e];
        g_idx[n] = arg;
        g_pmax[n] = 1.0f / s;
    }
}

// ---------------- capacity scan ----------------
__global__ void __launch_bounds__(256) capacity_kernel(
    const int* __restrict__ capp, float* __restrict__ mask_out)
{
    __shared__ int sidx[Sdim];
    __shared__ float spm[Sdim];
    const int b = blockIdx.x, tid = threadIdx.x;
    for (int s = tid; s < Sdim; s += 256) {
        sidx[s] = g_idx[b * Sdim + s];
        spm[s]  = g_pmax[b * Sdim + s];
    }
    __syncthreads();
    if (tid < Edim) {
        const int e = tid;
        int cap = capp[0];
        if (cap > CAPMAX) cap = CAPMAX;
        int cnt = 0;
        const int base = (b * Edim + e) * CAPMAX;
        for (int s = 0; s < Sdim; s++) {
            if (sidx[s] == e) {
                cnt++;
                if (cnt <= cap) {
                    g_etok[base + cnt - 1] = s;
                    g_escale[base + cnt - 1] = spm[s];
                    mask_out[((size_t)(b * Sdim + s)) * Edim + e] = spm[s];
                }
            }
        }
        g_count[b * Edim + e] = cnt < cap ? cnt : cap;
    }
}

// ---------------- gather h rows into packed per-(b,e) fp32 buffers ----------------
__global__ void __launch_bounds__(256) gather_kernel()
{
    const int tid = threadIdx.x;
    const int row = blockIdx.x * 4 + (tid >> 6);   // 0..8191
    const int lane = tid & 63;
    const int combo = row >> 8, slot = row & 255;
    float4* dst = (float4*)(g_hg + (size_t)row * Ddim) + lane * 2;
    if (slot < g_count[combo]) {
        const int tok = g_etok[row];
        const int b = combo >> 3;
        const float4* src = (const float4*)(g_h + ((size_t)(b * Sdim + tok)) * Ddim) + lane * 2;
        dst[0] = src[0];
        dst[1] = src[1];
    } else {
        float4 z = {0.f, 0.f, 0.f, 0.f};
        dst[0] = z;
        dst[1] = z;
    }
}

// ---------------- MoE FFN1 (HMMA bf16-split): y = gelu(hg @ wi[e]) ----------------
// grid (Fdim/128, CAPMAX/128, 32), 256 threads.
__global__ void __launch_bounds__(256) moe_ffn1_hmma()
{
    const int combo = blockIdx.z;
    const int cnt = g_count[combo];
    const int bm = blockIdx.y * 128;
    if (bm >= cnt) return;
    const int e = combo & 7;
    const int bn = blockIdx.x * 128;

    const float* A = g_hg + (size_t)(combo * CAPMAX + bm) * Ddim;
    const __nv_bfloat16* Bh = g_w1h + ((size_t)e * Fdim + bn) * Ddim;
    const __nv_bfloat16* Bl = g_w1l + ((size_t)e * Fdim + bn) * Ddim;

    float c[2][8][4];
    hmma_nt<Ddim, Ddim, Ddim>(A, Bh, Bl, c);

    const int lane = threadIdx.x & 31, wid = threadIdx.x >> 5;
    const int wm = (wid & 3) * 32, wn = (wid >> 2) * 64;
    const int mrow0 = combo * CAPMAX + bm + wm + lane / 4;
    const int ncol = bn + wn + (lane & 3) * 2;
#pragma unroll
    for (int i = 0; i < 2; i++) {
#pragma unroll
        for (int j = 0; j < 8; j++) {
            float* p0 = g_yg + (size_t)(mrow0 + i * 16) * Fdim + ncol + j * 8;
            float* p1 = p0 + 8 * Fdim;
            p0[0] = gelu_exact(c[i][j][0]);
            p0[1] = gelu_exact(c[i][j][1]);
            p1[0] = gelu_exact(c[i][j][2]);
            p1[1] = gelu_exact(c[i][j][3]);
        }
    }
}

// ---------------- MoE FFN2 (HMMA bf16-split): scatter((y @ wo[e]) * scale) ----------------
// grid (Ddim/128, CAPMAX/128, 32), 256 threads.
__global__ void __launch_bounds__(256) moe_ffn2_hmma()
{
    const int combo = blockIdx.z;
    const int cnt = g_count[combo];
    const int bm = blockIdx.y * 128;
    if (bm >= cnt) return;
    const int e = combo & 7;
    const int b = combo >> 3;
    const int bn = blockIdx.x * 128;

    const float* A = g_yg + (size_t)(combo * CAPMAX + bm) * Fdim;
    const __nv_bfloat16* Bh = g_w2h + ((size_t)e * Ddim + bn) * Fdim;
    const __nv_bfloat16* Bl = g_w2l + ((size_t)e * Ddim + bn) * Fdim;

    float c[2][8][4];
    hmma_nt<Fdim, Fdim, Fdim>(A, Bh, Bl, c);

    const int lane = threadIdx.x & 31, wid = threadIdx.x >> 5;
    const int wm = (wid & 3) * 32, wn = (wid >> 2) * 64;
    const int ncol = bn + wn + (lane & 3) * 2;
#pragma unroll
    for (int i = 0; i < 2; i++) {
        const int m0 = bm + wm + i * 16 + lane / 4;
#pragma unroll
        for (int half = 0; half < 2; half++) {
            const int m = m0 + half * 8;
            if (m < cnt) {
                const int tok = g_etok[combo * CAPMAX + m];
                const float sc = g_escale[combo * CAPMAX + m];
                float* op = g_moe + ((size_t)(b * Sdim + tok)) * Ddim + ncol;
#pragma unroll
                for (int j = 0; j < 8; j++) {
                    float2 v;
                    v.x = sc * c[i][j][half * 2 + 0];
                    v.y = sc * c[i][j][half * 2 + 1];
                    *(float2*)(op + j * 8) = v;
                }
            }
        }
    }
}

// ---------------- launch ----------------
extern "C" void kernel_launch(void* const* d_in, const int* in_sizes, int n_in,
                              void* d_out, int out_size)
{
    const float* x     = (const float*)d_in[0];
    const float* in_w  = (const float*)d_in[1];
    const float* in_b  = (const float*)d_in[2];
    const float* out_w = (const float*)d_in[3];
    const float* out_b = (const float*)d_in[4];
    const float* ln1g  = (const float*)d_in[5];
    const float* ln1b  = (const float*)d_in[6];
    const float* ln2g  = (const float*)d_in[7];
    const float* ln2b  = (const float*)d_in[8];
    const float* rw    = (const float*)d_in[9];
    const float* wi    = (const float*)d_in[10];
    const float* wo    = (const float*)d_in[11];
    const int*   cap   = (const int*)d_in[12];

    float* out        = (float*)d_out;
    float* logits_out = out + (size_t)NTOK * Ddim;
    float* mask_out   = logits_out + (size_t)NTOK * Edim;

    float *p_qkv, *p_attn, *p_aout, *p_h, *p_moe;
    __nv_bfloat16 *p_w1h, *p_w1l, *p_w2h, *p_w2l;
    cudaGetSymbolAddress((void**)&p_qkv,  g_qkv);
    cudaGetSymbolAddress((void**)&p_attn, g_attn);
    cudaGetSymbolAddress((void**)&p_aout, g_aout);
    cudaGetSymbolAddress((void**)&p_h,    g_h);
    cudaGetSymbolAddress((void**)&p_moe,  g_moe);
    cudaGetSymbolAddress((void**)&p_w1h,  g_w1h);
    cudaGetSymbolAddress((void**)&p_w1l,  g_w1l);
    cudaGetSymbolAddress((void**)&p_w2h,  g_w2h);
    cudaGetSymbolAddress((void**)&p_w2l,  g_w2l);

    const int fa_smem = FA_SMEM_FLOATS * (int)sizeof(float);
    cudaFuncSetAttribute(flash_attn_kernel,
                         cudaFuncAttributeMaxDynamicSharedMemorySize, fa_smem);

    // 0) weight transpose + bf16 split (independent of activation path)
    transpose_split_kernel<<<dim3(Fdim / 32, Ddim / 32, Edim), 256>>>(wi, p_w1h, p_w1l, Ddim, Fdim);
    transpose_split_kernel<<<dim3(Ddim / 32, Fdim / 32, Edim), 256>>>(wo, p_w2h, p_w2l, Fdim, Ddim);

    // 1) QKV projection (fp32)
    gemm_nt_bias_kernel<<<dim3(QKVW / 128, NTOK / 128), 256>>>(
        x, in_w, in_b, p_qkv, NTOK, QKVW, Ddim);

    // 2) fused attention (fp32)
    flash_attn_kernel<<<dim3(Sdim / 64, Hdim, Bdim), 256, fa_smem>>>(p_qkv, p_attn);

    // 3) output projection (fp32)
    gemm_nt_bias_kernel<<<dim3(Ddim / 128, NTOK / 128), 256>>>(
        p_attn, out_w, out_b, p_aout, NTOK, Ddim, Ddim);

    // 4) h = LN1(x + attn_out)
    add_ln_kernel<<<NTOK, 128>>>(p_aout, x, ln1g, ln1b, p_h);

    // 5) zero moe buffer + mask output
    zero_kernel<<<(NTOK * Ddim + 255) / 256, 256>>>(p_moe, NTOK * Ddim);
    zero_kernel<<<(NTOK * Edim + 255) / 256, 256>>>(mask_out, NTOK * Edim);

    // 6) router
    router_kernel<<<NTOK / 8, 256>>>(p_h, rw, logits_out);

    // 7) capacity scan
    capacity_kernel<<<Bdim, 256>>>(cap, mask_out);

    // 8) gather routed tokens (fp32)
    gather_kernel<<<(32 * CAPMAX) / 4, 256>>>();

    // 9) expert FFN on tensor cores (HMMA bf16 split)
    moe_ffn1_hmma<<<dim3(Fdim / 128, CAPMAX / 128, 32), 256>>>();
    moe_ffn2_hmma<<<dim3(Ddim / 128, CAPMAX / 128, 32), 256>>>();

    // 10) out = LN2(h + moe)
    add_ln_kernel<<<NTOK, 128>>>(p_moe, p_h, ln2g, ln2b, out);
}

// round 4
// speedup vs baseline: 1.5566x; 1.5566x over previous
#include <cuda_runtime.h>
#include <cuda_bf16.h>
#include <math.h>

typedef unsigned int u32;
typedef unsigned long long u64;

// Problem constants
#define Bdim 4
#define Sdim 1024
#define Ddim 512
#define Fdim 2048
#define Hdim 8
#define Edim 8
#define HD 64
#define NTOK 4096        // B*S
#define CAPMAX 256
#define QKVW 1536        // 3*D

// ---------------- scratch (device globals; no allocation) ----------------
__device__ float g_qkv [NTOK * QKVW];
__device__ float g_attn[NTOK * Ddim];
__device__ float g_aout[NTOK * Ddim];
__device__ float g_h   [NTOK * Ddim];
__device__ float g_moe [NTOK * Ddim];
__device__ float g_hg  [32 * CAPMAX * Ddim];          // gathered tokens fp32
__device__ float g_yg  [32 * CAPMAX * Fdim];          // FFN1 out fp32
__device__ __nv_bfloat16 g_w1h[Edim * Fdim * Ddim];   // wi^T  [e][f][d] hi
__device__ __nv_bfloat16 g_w1l[Edim * Fdim * Ddim];
__device__ __nv_bfloat16 g_w2h[Edim * Ddim * Fdim];   // wo^T  [e][d][f] hi
__device__ __nv_bfloat16 g_w2l[Edim * Ddim * Fdim];
__device__ int   g_idx [NTOK];
__device__ float g_pmax[NTOK];
__device__ int   g_etok[32 * CAPMAX];
__device__ float g_escale[32 * CAPMAX];
__device__ int   g_count[32];

// ---------------- small helpers ----------------
__device__ __forceinline__ u32 smem_u32(const void* p) {
    u32 a;
    asm("{ .reg .u64 t; cvta.to.shared.u64 t, %1; cvt.u32.u64 %0, t; }" : "=r"(a) : "l"(p));
    return a;
}
__device__ __forceinline__ u32 bfpack(__nv_bfloat16 a, __nv_bfloat16 b) {
    __nv_bfloat162 t;
    t.x = a; t.y = b;
    return *(u32*)&t;
}
__device__ __forceinline__ void ldm4(u32 r[4], u32 addr) {
    asm volatile("ldmatrix.sync.aligned.m8n8.x4.shared.b16 {%0,%1,%2,%3}, [%4];"
                 : "=r"(r[0]), "=r"(r[1]), "=r"(r[2]), "=r"(r[3]) : "r"(addr));
}
__device__ __forceinline__ void mma16816(float c[4], const u32 a[4], const u32 b[2]) {
    asm volatile(
        "mma.sync.aligned.m16n8k16.row.col.f32.bf16.bf16.f32 "
        "{%0,%1,%2,%3}, {%4,%5,%6,%7}, {%8,%9}, {%0,%1,%2,%3};"
        : "+f"(c[0]), "+f"(c[1]), "+f"(c[2]), "+f"(c[3])
        : "r"(a[0]), "r"(a[1]), "r"(a[2]), "r"(a[3]), "r"(b[0]), "r"(b[1]));
}
__device__ __forceinline__ float gelu_exact(float x) {
    return 0.5f * x * (1.0f + erff(x * 0.70710678118654752f));
}

// ---------------- HMMA bf16-split NT mainloop ----------------
// Block tile 128x128, 256 threads (8 warps, 4M x 2N), warp tile 32x64.
// A: fp32 [128 rows x K] (row stride LDA), split to bf16 hi/lo on smem store.
// B: pre-split bf16 hi/lo [128 rows(N) x K] (row stride LDB).
// C = A@B^T in c[2][8][4] fragments (3-pass precision split).
template<int LDA, int LDB, int KTOT>
__device__ __forceinline__ void hmma_nt(
    const float* __restrict__ A,
    const __nv_bfloat16* __restrict__ Bh, const __nv_bfloat16* __restrict__ Bl,
    float (&c)[2][8][4])
{
    __shared__ __align__(16) char Ash[128 * 80];
    __shared__ __align__(16) char Asl[128 * 80];
    __shared__ __align__(16) char Bsh[128 * 80];
    __shared__ __align__(16) char Bsl[128 * 80];

    const int tid = threadIdx.x;
    const int lane = tid & 31, wid = tid >> 5;
    const int wm = (wid & 3) * 32, wn = (wid >> 2) * 64;
    const u32 a_base  = smem_u32(Ash);
    const u32 al_base = smem_u32(Asl);
    const u32 b_base  = smem_u32(Bsh);
    const u32 bl_base = smem_u32(Bsl);
    const int rowA = (lane & 7) + ((lane >> 3) & 1) * 8;
    const int colA = (lane >> 4) * 16;
    const int rowB = (lane & 7) + (lane >> 4) * 8;
    const int colB = ((lane >> 3) & 1) * 16;

#pragma unroll
    for (int i = 0; i < 2; i++)
#pragma unroll
        for (int j = 0; j < 8; j++)
#pragma unroll
            for (int q = 0; q < 4; q++) c[i][j][q] = 0.0f;

    for (int k0 = 0; k0 < KTOT; k0 += 32) {
        __syncthreads();
        // A: 128 rows x 32 fp32 -> bf16 hi/lo
#pragma unroll
        for (int i = 0; i < 4; i++) {
            int t = tid + i * 256;
            int r = t >> 3, kq = t & 7;
            float4 v = *(const float4*)(A + (size_t)r * LDA + k0 + kq * 4);
            __nv_bfloat16 h0 = __float2bfloat16(v.x);
            __nv_bfloat16 h1 = __float2bfloat16(v.y);
            __nv_bfloat16 h2 = __float2bfloat16(v.z);
            __nv_bfloat16 h3 = __float2bfloat16(v.w);
            __nv_bfloat16 l0 = __float2bfloat16(v.x - __bfloat162float(h0));
            __nv_bfloat16 l1 = __float2bfloat16(v.y - __bfloat162float(h1));
            __nv_bfloat16 l2 = __float2bfloat16(v.z - __bfloat162float(h2));
            __nv_bfloat16 l3 = __float2bfloat16(v.w - __bfloat162float(h3));
            u32 off = r * 80 + kq * 8;
            ((u32*)(Ash + off))[0] = bfpack(h0, h1);
            ((u32*)(Ash + off))[1] = bfpack(h2, h3);
            ((u32*)(Asl + off))[0] = bfpack(l0, l1);
            ((u32*)(Asl + off))[1] = bfpack(l2, l3);
        }
        // B: 128 rows x 32 bf16 hi/lo
#pragma unroll
        for (int i = 0; i < 2; i++) {
            int t = tid + i * 256;
            int r = t >> 2, kq = t & 3;
            *(uint4*)(Bsh + r * 80 + kq * 16) = *(const uint4*)(Bh + (size_t)r * LDB + k0 + kq * 8);
            *(uint4*)(Bsl + r * 80 + kq * 16) = *(const uint4*)(Bl + (size_t)r * LDB + k0 + kq * 8);
        }
        __syncthreads();
#pragma unroll
        for (int kk = 0; kk < 32; kk += 16) {
            u32 ah[2][4], al2[2][4], bhf[8][2], blf[8][2];
#pragma unroll
            for (int s = 0; s < 2; s++) {
                ldm4(ah[s],  a_base  + (wm + s * 16 + rowA) * 80 + kk * 2 + colA);
                ldm4(al2[s], al_base + (wm + s * 16 + rowA) * 80 + kk * 2 + colA);
            }
#pragma unroll
            for (int p = 0; p < 4; p++) {
                u32 t4[4];
                ldm4(t4, b_base + (wn + p * 16 + rowB) * 80 + kk * 2 + colB);
                bhf[2 * p][0] = t4[0]; bhf[2 * p][1] = t4[1];
                bhf[2 * p + 1][0] = t4[2]; bhf[2 * p + 1][1] = t4[3];
                ldm4(t4, bl_base + (wn + p * 16 + rowB) * 80 + kk * 2 + colB);
                blf[2 * p][0] = t4[0]; blf[2 * p][1] = t4[1];
                blf[2 * p + 1][0] = t4[2]; blf[2 * p + 1][1] = t4[3];
            }
#pragma unroll
            for (int i2 = 0; i2 < 2; i2++)
#pragma unroll
                for (int j = 0; j < 8; j++) {
                    mma16816(c[i2][j], ah[i2],  bhf[j]);
                    mma16816(c[i2][j], ah[i2],  blf[j]);
                    mma16816(c[i2][j], al2[i2], bhf[j]);
                }
        }
    }
}

// ---------------- generic zero ----------------
__global__ void zero_kernel(float* __restrict__ p, int n) {
    int i = blockIdx.x * blockDim.x + threadIdx.x;
    if (i < n) p[i] = 0.0f;
}

// ---------------- weight transpose + bf16 split: src[m][R][C] -> dst[m][C][R] ----------------
__global__ void __launch_bounds__(256) transpose_split_kernel(
    const float* __restrict__ src, __nv_bfloat16* __restrict__ dh,
    __nv_bfloat16* __restrict__ dl, int R, int C)
{
    __shared__ float t[32][33];
    const int m = blockIdx.z;
    const int c0 = blockIdx.x * 32, r0 = blockIdx.y * 32;
    const int tx = threadIdx.x & 31, ty = threadIdx.x >> 5;
    const float* s = src + (size_t)m * R * C;
#pragma unroll
    for (int j = 0; j < 32; j += 8)
        t[ty + j][tx] = s[(size_t)(r0 + ty + j) * C + c0 + tx];
    __syncthreads();
    const size_t obase = (size_t)m * R * C;
#pragma unroll
    for (int j = 0; j < 32; j += 8) {
        float v = t[tx][ty + j];
        __nv_bfloat16 h = __float2bfloat16(v);
        __nv_bfloat16 l = __float2bfloat16(v - __bfloat162float(h));
        dh[obase + (size_t)(c0 + ty + j) * R + r0 + tx] = h;
        dl[obase + (size_t)(c0 + ty + j) * R + r0 + tx] = l;
    }
}

// ---------------- GEMM NT + bias (fp32 FFMA): C[M,N] = A[M,K] @ B[N,K]^T + bias ----------------
__global__ void __launch_bounds__(256) gemm_nt_bias_kernel(
    const float* __restrict__ A, const float* __restrict__ Bm,
    const float* __restrict__ bias, float* __restrict__ C,
    int M, int N, int K)
{
    __shared__ float As[8][128];
    __shared__ float Bs[8][128];
    const int bm = blockIdx.y * 128;
    const int bn = blockIdx.x * 128;
    const int tid = threadIdx.x;
    const int tx = tid & 15, ty = tid >> 4;
    const int lr = tid >> 1;
    const int lk = (tid & 1) * 4;
    const float* Aptr = A + (size_t)(bm + lr) * K + lk;
    const float* Bptr = Bm + (size_t)(bn + lr) * K + lk;

    float acc[8][8];
#pragma unroll
    for (int i = 0; i < 8; i++)
#pragma unroll
        for (int j = 0; j < 8; j++) acc[i][j] = 0.0f;

    for (int k0 = 0; k0 < K; k0 += 8) {
        float4 av = *(const float4*)(Aptr + k0);
        float4 bv = *(const float4*)(Bptr + k0);
        As[lk + 0][lr] = av.x; As[lk + 1][lr] = av.y;
        As[lk + 2][lr] = av.z; As[lk + 3][lr] = av.w;
        Bs[lk + 0][lr] = bv.x; Bs[lk + 1][lr] = bv.y;
        Bs[lk + 2][lr] = bv.z; Bs[lk + 3][lr] = bv.w;
        __syncthreads();
#pragma unroll
        for (int kk = 0; kk < 8; kk++) {
            float a[8], b[8];
#pragma unroll
            for (int i = 0; i < 8; i++) a[i] = As[kk][ty * 8 + i];
#pragma unroll
            for (int j = 0; j < 8; j++) b[j] = Bs[kk][tx * 8 + j];
#pragma unroll
            for (int i = 0; i < 8; i++)
#pragma unroll
                for (int j = 0; j < 8; j++)
                    acc[i][j] = fmaf(a[i], b[j], acc[i][j]);
        }
        __syncthreads();
    }
#pragma unroll
    for (int i = 0; i < 8; i++) {
        int row = bm + ty * 8 + i;
        float* cp = C + (size_t)row * N + bn + tx * 8;
#pragma unroll
        for (int j = 0; j < 8; j++) cp[j] = acc[i][j] + bias[bn + tx * 8 + j];
    }
}

// ---------------- flash attention (fp32, hd=64) ----------------
#define FA_SMEM_FLOATS (3 * 64 * 65 + 4 * 64 + 3 * 64)
__global__ void __launch_bounds__(256) flash_attn_kernel(
    const float* __restrict__ qkv, float* __restrict__ out)
{
    extern __shared__ float smf[];
    float* Qs   = smf;
    float* KVs  = Qs + 64 * 65;
    float* Ps   = KVs + 64 * 65;
    float* psum = Ps + 64 * 65;
    float* mrow = psum + 256;
    float* lrow = mrow + 64;
    float* arow = lrow + 64;

    const int qt = blockIdx.x, h = blockIdx.y, b = blockIdx.z;
    const int tid = threadIdx.x;
    const int tx = tid & 15, ty = tid >> 4;
    const int q0 = qt * 64;
    const float scale = 0.125f;

    {
        int r = tid >> 2;
        int c0 = (tid & 3) * 16;
        const float* src = qkv + ((size_t)(b * Sdim + q0 + r)) * QKVW + h * HD + c0;
#pragma unroll
        for (int i = 0; i < 4; i++) {
            float4 v = *(const float4*)(src + 4 * i);
            Qs[r * 65 + c0 + 4 * i + 0] = v.x * scale;
            Qs[r * 65 + c0 + 4 * i + 1] = v.y * scale;
            Qs[r * 65 + c0 + 4 * i + 2] = v.z * scale;
            Qs[r * 65 + c0 + 4 * i + 3] = v.w * scale;
        }
    }
    if (tid < 64) { mrow[tid] = -1e30f; lrow[tid] = 0.0f; }

    float acc[4][4];
#pragma unroll
    for (int i = 0; i < 4; i++)
#pragma unroll
        for (int j = 0; j < 4; j++) acc[i][j] = 0.0f;

    for (int kt = 0; kt < 16; kt++) {
        __syncthreads();
        {
            int r = tid >> 2;
            int c0 = (tid & 3) * 16;
            const float* src = qkv + ((size_t)(b * Sdim + kt * 64 + r)) * QKVW + Ddim + h * HD + c0;
#pragma unroll
            for (int i = 0; i < 4; i++) {
                float4 v = *(const float4*)(src + 4 * i);
                KVs[r * 65 + c0 + 4 * i + 0] = v.x;
                KVs[r * 65 + c0 + 4 * i + 1] = v.y;
                KVs[r * 65 + c0 + 4 * i + 2] = v.z;
                KVs[r * 65 + c0 + 4 * i + 3] = v.w;
            }
        }
        __syncthreads();
        float sacc[4][4];
#pragma unroll
        for (int i = 0; i < 4; i++)
#pragma unroll
            for (int j = 0; j < 4; j++) sacc[i][j] = 0.0f;
#pragma unroll 4
        for (int kk = 0; kk < 64; kk++) {
            float qv[4], kv[4];
#pragma unroll
            for (int i = 0; i < 4; i++) qv[i] = Qs[(ty * 4 + i) * 65 + kk];
#pragma unroll
            for (int j = 0; j < 4; j++) kv[j] = KVs[(tx * 4 + j) * 65 + kk];
#pragma unroll
            for (int i = 0; i < 4; i++)
#pragma unroll
                for (int j = 0; j < 4; j++)
                    sacc[i][j] = fmaf(qv[i], kv[j], sacc[i][j]);
        }
#pragma unroll
        for (int i = 0; i < 4; i++)
#pragma unroll
            for (int j = 0; j < 4; j++)
                Ps[(ty * 4 + i) * 65 + tx * 4 + j] = sacc[i][j];
        __syncthreads();
        {
            int r = tid >> 2;
            int c0 = (tid & 3) * 16;
            const float* src = qkv + ((size_t)(b * Sdim + kt * 64 + r)) * QKVW + 2 * Ddim + h * HD + c0;
#pragma unroll
            for (int i = 0; i < 4; i++) {
                float4 v = *(const float4*)(src + 4 * i);
                KVs[r * 65 + c0 + 4 * i + 0] = v.x;
                KVs[r * 65 + c0 + 4 * i + 1] = v.y;
                KVs[r * 65 + c0 + 4 * i + 2] = v.z;
                KVs[r * 65 + c0 + 4 * i + 3] = v.w;
            }
        }
        if (tid < 64) {
            float m = mrow[tid];
#pragma unroll 8
            for (int c = 0; c < 64; c++) m = fmaxf(m, Ps[tid * 65 + c]);
            arow[tid] = __expf(mrow[tid] - m);
            mrow[tid] = m;
        }
        __syncthreads();
        {
            int row = tid & 63, qq = tid >> 6;
            float m = mrow[row];
            float s = 0.0f;
            int c0 = qq * 16;
#pragma unroll
            for (int c = c0; c < c0 + 16; c++) {
                float p = __expf(Ps[row * 65 + c] - m);
                Ps[row * 65 + c] = p;
                s += p;
            }
            psum[qq * 64 + row] = s;
        }
        __syncthreads();
        if (tid < 64)
            lrow[tid] = arow[tid] * lrow[tid] + psum[tid] + psum[64 + tid] + psum[128 + tid] + psum[192 + tid];
        {
            float al[4];
#pragma unroll
            for (int i = 0; i < 4; i++) al[i] = arow[ty * 4 + i];
#pragma unroll
            for (int i = 0; i < 4; i++)
#pragma unroll
                for (int j = 0; j < 4; j++) acc[i][j] *= al[i];
        }
#pragma unroll 4
        for (int kk = 0; kk < 64; kk++) {
            float pv[4], vv[4];
#pragma unroll
            for (int i = 0; i < 4; i++) pv[i] = Ps[(ty * 4 + i) * 65 + kk];
#pragma unroll
            for (int j = 0; j < 4; j++) vv[j] = KVs[kk * 65 + tx * 4 + j];
#pragma unroll
            for (int i = 0; i < 4; i++)
#pragma unroll
                for (int j = 0; j < 4; j++)
                    acc[i][j] = fmaf(pv[i], vv[j], acc[i][j]);
        }
    }
    __syncthreads();
    float inv[4];
#pragma unroll
    for (int i = 0; i < 4; i++) inv[i] = 1.0f / lrow[ty * 4 + i];
#pragma unroll
    for (int i = 0; i < 4; i++) {
        float* op = out + ((size_t)(b * Sdim + q0 + ty * 4 + i)) * Ddim + h * HD + tx * 4;
#pragma unroll
        for (int j = 0; j < 4; j++) op[j] = acc[i][j] * inv[i];
    }
}

// ---------------- fused residual add + LayerNorm ----------------
__global__ void __launch_bounds__(128) add_ln_kernel(
    const float* __restrict__ a, const float* __restrict__ r,
    const float* __restrict__ g, const float* __restrict__ be,
    float* __restrict__ out)
{
    const int n = blockIdx.x;
    const int tid = threadIdx.x;
    __shared__ float red[4], red2[4];
    __shared__ float s_mu, s_rstd;
    const float* ap = a + (size_t)n * Ddim;
    const float* rp = r + (size_t)n * Ddim;
    float v[4];
    float sum = 0.0f, sq = 0.0f;
#pragma unroll
    for (int i = 0; i < 4; i++) {
        v[i] = ap[tid + i * 128] + rp[tid + i * 128];
        sum += v[i];
        sq = fmaf(v[i], v[i], sq);
    }
#pragma unroll
    for (int o = 16; o; o >>= 1) {
        sum += __shfl_xor_sync(0xffffffffu, sum, o);
        sq  += __shfl_xor_sync(0xffffffffu, sq, o);
    }
    if ((tid & 31) == 0) { red[tid >> 5] = sum; red2[tid >> 5] = sq; }
    __syncthreads();
    if (tid == 0) {
        float s = red[0] + red[1] + red[2] + red[3];
        float q = red2[0] + red2[1] + red2[2] + red2[3];
        float mu = s * (1.0f / 512.0f);
        float var = q * (1.0f / 512.0f) - mu * mu;
        s_mu = mu;
        s_rstd = rsqrtf(var + 1e-5f);
    }
    __syncthreads();
    float mu = s_mu, rstd = s_rstd;
#pragma unroll
    for (int i = 0; i < 4; i++) {
        int d = tid + i * 128;
        out[(size_t)n * Ddim + d] = (v[i] - mu) * rstd * g[d] + be[d];
    }
}

// ---------------- router: logits + softmax + argmax ----------------
__global__ void __launch_bounds__(256) router_kernel(
    const float* __restrict__ h, const float* __restrict__ rw,
    float* __restrict__ logits_out)
{
    const int w = threadIdx.x >> 5, l = threadIdx.x & 31;
    const int n = blockIdx.x * 8 + w;
    float acc[8];
#pragma unroll
    for (int e = 0; e < 8; e++) acc[e] = 0.0f;
    const float* hp = h + (size_t)n * Ddim;
    for (int d = l; d < Ddim; d += 32) {
        float hv = hp[d];
        const float4* rp = (const float4*)(rw + d * 8);
        float4 r0 = rp[0], r1 = rp[1];
        acc[0] = fmaf(hv, r0.x, acc[0]); acc[1] = fmaf(hv, r0.y, acc[1]);
        acc[2] = fmaf(hv, r0.z, acc[2]); acc[3] = fmaf(hv, r0.w, acc[3]);
        acc[4] = fmaf(hv, r1.x, acc[4]); acc[5] = fmaf(hv, r1.y, acc[5]);
        acc[6] = fmaf(hv, r1.z, acc[6]); acc[7] = fmaf(hv, r1.w, acc[7]);
    }
#pragma unroll
    for (int e = 0; e < 8; e++)
#pragma unroll
        for (int o = 16; o; o >>= 1)
            acc[e] += __shfl_xor_sync(0xffffffffu, acc[e], o);
    if (l == 0) {
        float m = acc[0]; int arg = 0;
#pragma unroll
        for (int e = 1; e < 8; e++) if (acc[e] > m) { m = acc[e]; arg = e; }
        float s = 0.0f;
#pragma unroll
        for (int e = 0; e < 8; e++) s += __expf(acc[e] - m);
#pragma unroll
        for (int e = 0; e < 8; e++) logits_out[(size_t)n * 8 + e] = acc[e];
        g_idx[n] = arg;
        g_pmax[n] = 1.0f / s;
    }
}

// ---------------- capacity scan ----------------
__global__ void __launch_bounds__(256) capacity_kernel(
    const int* __restrict__ capp, float* __restrict__ mask_out)
{
    __shared__ int sidx[Sdim];
    __shared__ float spm[Sdim];
    const int b = blockIdx.x, tid = threadIdx.x;
    for (int s = tid; s < Sdim; s += 256) {
        sidx[s] = g_idx[b * Sdim + s];
        spm[s]  = g_pmax[b * Sdim + s];
    }
    __syncthreads();
    if (tid < Edim) {
        const int e = tid;
        int cap = capp[0];
        if (cap > CAPMAX) cap = CAPMAX;
        int cnt = 0;
        const int base = (b * Edim + e) * CAPMAX;
        for (int s = 0; s < Sdim; s++) {
            if (sidx[s] == e) {
                cnt++;
                if (cnt <= cap) {
                    g_etok[base + cnt - 1] = s;
                    g_escale[base + cnt - 1] = spm[s];
                    mask_out[((size_t)(b * Sdim + s)) * Edim + e] = spm[s];
                }
            }
        }
        g_count[b * Edim + e] = cnt < cap ? cnt : cap;
    }
}

// ---------------- gather h rows into packed per-(b,e) fp32 buffers ----------------
__global__ void __launch_bounds__(256) gather_kernel()
{
    const int tid = threadIdx.x;
    const int row = blockIdx.x * 4 + (tid >> 6);   // 0..8191
    const int lane = tid & 63;
    const int combo = row >> 8, slot = row & 255;
    float4* dst = (float4*)(g_hg + (size_t)row * Ddim) + lane * 2;
    if (slot < g_count[combo]) {
        const int tok = g_etok[row];
        const int b = combo >> 3;
        const float4* src = (const float4*)(g_h + ((size_t)(b * Sdim + tok)) * Ddim) + lane * 2;
        dst[0] = src[0];
        dst[1] = src[1];
    } else {
        float4 z = {0.f, 0.f, 0.f, 0.f};
        dst[0] = z;
        dst[1] = z;
    }
}

// ---------------- MoE FFN1 (HMMA bf16-split): y = gelu(hg @ wi[e]) ----------------
// grid (Fdim/128, CAPMAX/128, 32), 256 threads.
__global__ void __launch_bounds__(256) moe_ffn1_hmma()
{
    const int combo = blockIdx.z;
    const int cnt = g_count[combo];
    const int bm = blockIdx.y * 128;
    if (bm >= cnt) return;
    const int e = combo & 7;
    const int bn = blockIdx.x * 128;

    const float* A = g_hg + (size_t)(combo * CAPMAX + bm) * Ddim;
    const __nv_bfloat16* Bh = g_w1h + ((size_t)e * Fdim + bn) * Ddim;
    const __nv_bfloat16* Bl = g_w1l + ((size_t)e * Fdim + bn) * Ddim;

    float c[2][8][4];
    hmma_nt<Ddim, Ddim, Ddim>(A, Bh, Bl, c);

    const int lane = threadIdx.x & 31, wid = threadIdx.x >> 5;
    const int wm = (wid & 3) * 32, wn = (wid >> 2) * 64;
    const int mrow0 = combo * CAPMAX + bm + wm + lane / 4;
    const int ncol = bn + wn + (lane & 3) * 2;
#pragma unroll
    for (int i = 0; i < 2; i++) {
#pragma unroll
        for (int j = 0; j < 8; j++) {
            float* p0 = g_yg + (size_t)(mrow0 + i * 16) * Fdim + ncol + j * 8;
            float* p1 = p0 + 8 * Fdim;
            p0[0] = gelu_exact(c[i][j][0]);
            p0[1] = gelu_exact(c[i][j][1]);
            p1[0] = gelu_exact(c[i][j][2]);
            p1[1] = gelu_exact(c[i][j][3]);
        }
    }
}

// ---------------- MoE FFN2 (HMMA bf16-split): scatter((y @ wo[e]) * scale) ----------------
// grid (Ddim/128, CAPMAX/128, 32), 256 threads.
__global__ void __launch_bounds__(256) moe_ffn2_hmma()
{
    const int combo = blockIdx.z;
    const int cnt = g_count[combo];
    const int bm = blockIdx.y * 128;
    if (bm >= cnt) return;
    const int e = combo & 7;
    const int b = combo >> 3;
    const int bn = blockIdx.x * 128;

    const float* A = g_yg + (size_t)(combo * CAPMAX + bm) * Fdim;
    const __nv_bfloat16* Bh = g_w2h + ((size_t)e * Ddim + bn) * Fdim;
    const __nv_bfloat16* Bl = g_w2l + ((size_t)e * Ddim + bn) * Fdim;

    float c[2][8][4];
    hmma_nt<Fdim, Fdim, Fdim>(A, Bh, Bl, c);

    const int lane = threadIdx.x & 31, wid = threadIdx.x >> 5;
    const int wm = (wid & 3) * 32, wn = (wid >> 2) * 64;
    const int ncol = bn + wn + (lane & 3) * 2;
#pragma unroll
    for (int i = 0; i < 2; i++) {
        const int m0 = bm + wm + i * 16 + lane / 4;
#pragma unroll
        for (int half = 0; half < 2; half++) {
            const int m = m0 + half * 8;
            if (m < cnt) {
                const int tok = g_etok[combo * CAPMAX + m];
                const float sc = g_escale[combo * CAPMAX + m];
                float* op = g_moe + ((size_t)(b * Sdim + tok)) * Ddim + ncol;
#pragma unroll
                for (int j = 0; j < 8; j++) {
                    float2 v;
                    v.x = sc * c[i][j][half * 2 + 0];
                    v.y = sc * c[i][j][half * 2 + 1];
                    *(float2*)(op + j * 8) = v;
                }
            }
        }
    }
}

// ---------------- launch ----------------
extern "C" void kernel_launch(void* const* d_in, const int* in_sizes, int n_in,
                              void* d_out, int out_size)
{
    const float* x     = (const float*)d_in[0];
    const float* in_w  = (const float*)d_in[1];
    const float* in_b  = (const float*)d_in[2];
    const float* out_w = (const float*)d_in[3];
    const float* out_b = (const float*)d_in[4];
    const float* ln1g  = (const float*)d_in[5];
    const float* ln1b  = (const float*)d_in[6];
    const float* ln2g  = (const float*)d_in[7];
    const float* ln2b  = (const float*)d_in[8];
    const float* rw    = (const float*)d_in[9];
    const float* wi    = (const float*)d_in[10];
    const float* wo    = (const float*)d_in[11];
    const int*   cap   = (const int*)d_in[12];

    float* out        = (float*)d_out;
    float* logits_out = out + (size_t)NTOK * Ddim;
    float* mask_out   = logits_out + (size_t)NTOK * Edim;

    float *p_qkv, *p_attn, *p_aout, *p_h, *p_moe;
    __nv_bfloat16 *p_w1h, *p_w1l, *p_w2h, *p_w2l;
    cudaGetSymbolAddress((void**)&p_qkv,  g_qkv);
    cudaGetSymbolAddress((void**)&p_attn, g_attn);
    cudaGetSymbolAddress((void**)&p_aout, g_aout);
    cudaGetSymbolAddress((void**)&p_h,    g_h);
    cudaGetSymbolAddress((void**)&p_moe,  g_moe);
    cudaGetSymbolAddress((void**)&p_w1h,  g_w1h);
    cudaGetSymbolAddress((void**)&p_w1l,  g_w1l);
    cudaGetSymbolAddress((void**)&p_w2h,  g_w2h);
    cudaGetSymbolAddress((void**)&p_w2l,  g_w2l);

    const int fa_smem = FA_SMEM_FLOATS * (int)sizeof(float);
    cudaFuncSetAttribute(flash_attn_kernel,
                         cudaFuncAttributeMaxDynamicSharedMemorySize, fa_smem);

    // 0) weight transpose + bf16 split (independent of activation path)
    transpose_split_kernel<<<dim3(Fdim / 32, Ddim / 32, Edim), 256>>>(wi, p_w1h, p_w1l, Ddim, Fdim);
    transpose_split_kernel<<<dim3(Ddim / 32, Fdim / 32, Edim), 256>>>(wo, p_w2h, p_w2l, Fdim, Ddim);

    // 1) QKV projection (fp32)
    gemm_nt_bias_kernel<<<dim3(QKVW / 128, NTOK / 128), 256>>>(
        x, in_w, in_b, p_qkv, NTOK, QKVW, Ddim);

    // 2) fused attention (fp32)
    flash_attn_kernel<<<dim3(Sdim / 64, Hdim, Bdim), 256, fa_smem>>>(p_qkv, p_attn);

    // 3) output projection (fp32)
    gemm_nt_bias_kernel<<<dim3(Ddim / 128, NTOK / 128), 256>>>(
        p_attn, out_w, out_b, p_aout, NTOK, Ddim, Ddim);

    // 4) h = LN1(x + attn_out)
    add_ln_kernel<<<NTOK, 128>>>(p_aout, x, ln1g, ln1b, p_h);

    // 5) zero moe buffer + mask output
    zero_kernel<<<(NTOK * Ddim + 255) / 256, 256>>>(p_moe, NTOK * Ddim);
    zero_kernel<<<(NTOK * Edim + 255) / 256, 256>>>(mask_out, NTOK * Edim);

    // 6) router
    router_kernel<<<NTOK / 8, 256>>>(p_h, rw, logits_out);

    // 7) capacity scan
    capacity_kernel<<<Bdim, 256>>>(cap, mask_out);

    // 8) gather routed tokens (fp32)
    gather_kernel<<<(32 * CAPMAX) / 4, 256>>>();

    // 9) expert FFN on tensor cores (HMMA bf16 split)
    moe_ffn1_hmma<<<dim3(Fdim / 128, CAPMAX / 128, 32), 256>>>();
    moe_ffn2_hmma<<<dim3(Ddim / 128, CAPMAX / 128, 32), 256>>>();

    // 10) out = LN2(h + moe)
    add_ln_kernel<<<NTOK, 128>>>(p_moe, p_h, ln2g, ln2b, out);
}

// round 5
// speedup vs baseline: 2.7686x; 1.7786x over previous
#include <cuda_runtime.h>
#include <cuda_bf16.h>
#include <math.h>

typedef unsigned int u32;
typedef unsigned long long u64;

#define Bdim 4
#define Sdim 1024
#define Ddim 512
#define Fdim 2048
#define Hdim 8
#define Edim 8
#define HD 64
#define NTOK 4096
#define CAPMAX 256
#define QKVW 1536

// ---------------- scratch ----------------
__device__ float g_qkv [NTOK * QKVW];
__device__ float g_aout[NTOK * Ddim];
__device__ float g_h   [NTOK * Ddim];
__device__ float g_moe [NTOK * Ddim];
__device__ __nv_bfloat16 g_xh [NTOK * Ddim], g_xl [NTOK * Ddim];
__device__ __nv_bfloat16 g_iwh[QKVW * Ddim], g_iwl[QKVW * Ddim];
__device__ __nv_bfloat16 g_owh[Ddim * Ddim], g_owl[Ddim * Ddim];
__device__ __nv_bfloat16 g_qh [NTOK * Ddim], g_ql [NTOK * Ddim];
__device__ __nv_bfloat16 g_kh [NTOK * Ddim], g_kl [NTOK * Ddim];
__device__ __nv_bfloat16 g_vth[Bdim * Ddim * Sdim], g_vtl[Bdim * Ddim * Sdim];
__device__ __nv_bfloat16 g_ah [NTOK * Ddim], g_al [NTOK * Ddim];
__device__ __nv_bfloat16 g_hgh[32 * CAPMAX * Ddim], g_hgl[32 * CAPMAX * Ddim];
__device__ __nv_bfloat16 g_ygh[32 * CAPMAX * Fdim], g_ygl[32 * CAPMAX * Fdim];
__device__ __nv_bfloat16 g_w1h[Edim * Fdim * Ddim], g_w1l[Edim * Fdim * Ddim];
__device__ __nv_bfloat16 g_w2h[Edim * Ddim * Fdim], g_w2l[Edim * Ddim * Fdim];
__device__ int   g_idx [NTOK];
__device__ float g_pmax[NTOK];
__device__ int   g_etok[32 * CAPMAX];
__device__ float g_escale[32 * CAPMAX];
__device__ int   g_count[32];

// ---------------- helpers ----------------
__device__ __forceinline__ u32 smem_u32(const void* p) {
    u32 a;
    asm("{ .reg .u64 t; cvta.to.shared.u64 t, %1; cvt.u32.u64 %0, t; }" : "=r"(a) : "l"(p));
    return a;
}
__device__ __forceinline__ u32 bfpack(__nv_bfloat16 a, __nv_bfloat16 b) {
    __nv_bfloat162 t; t.x = a; t.y = b; return *(u32*)&t;
}
__device__ __forceinline__ void ldm4(u32 r[4], u32 addr) {
    asm volatile("ldmatrix.sync.aligned.m8n8.x4.shared.b16 {%0,%1,%2,%3}, [%4];"
                 : "=r"(r[0]), "=r"(r[1]), "=r"(r[2]), "=r"(r[3]) : "r"(addr));
}
__device__ __forceinline__ void mma16816(float c[4], const u32 a[4], const u32 b[2]) {
    asm volatile(
        "mma.sync.aligned.m16n8k16.row.col.f32.bf16.bf16.f32 "
        "{%0,%1,%2,%3}, {%4,%5,%6,%7}, {%8,%9}, {%0,%1,%2,%3};"
        : "+f"(c[0]), "+f"(c[1]), "+f"(c[2]), "+f"(c[3])
        : "r"(a[0]), "r"(a[1]), "r"(a[2]), "r"(a[3]), "r"(b[0]), "r"(b[1]));
}
__device__ __forceinline__ void cp16(u32 dst, const void* src) {
    asm volatile("cp.async.cg.shared.global [%0], [%1], 16;" :: "r"(dst), "l"(src));
}
#define CP_COMMIT() asm volatile("cp.async.commit_group;" ::: "memory")
#define CP_WAIT1()  asm volatile("cp.async.wait_group 1;" ::: "memory")
#define CP_WAIT0()  asm volatile("cp.async.wait_group 0;" ::: "memory")
__device__ __forceinline__ float gelu_exact(float x) {
    return 0.5f * x * (1.0f + erff(x * 0.70710678118654752f));
}
__device__ __forceinline__ void split2(float v, __nv_bfloat16& h, __nv_bfloat16& l) {
    h = __float2bfloat16(v);
    l = __float2bfloat16(v - __bfloat162float(h));
}

// ========== pipelined HMMA bf16-split NT mainloop (128x128, 256 thr) ==========
#define GSTG 40960
#define GEMM_SMEM (2 * GSTG)

__device__ __forceinline__ void gemm_issue(
    u32 st, const __nv_bfloat16* Ah, const __nv_bfloat16* Al,
    const __nv_bfloat16* Bh, const __nv_bfloat16* Bl,
    int ldA, int ldB, int k0, int tid)
{
    int idx = tid;
#pragma unroll
    for (int t = 0; t < 8; t++, idx += 256) {
        int sel = idx >> 9;
        int q = idx & 511;
        int r = q >> 2, kq = q & 3;
        const __nv_bfloat16* src = (sel == 0 ? Ah : sel == 1 ? Al : sel == 2 ? Bh : Bl);
        int ld = (sel < 2) ? ldA : ldB;
        cp16(st + sel * 10240 + r * 80 + kq * 16, src + (size_t)r * ld + k0 + kq * 8);
    }
}

template<int K>
__device__ __forceinline__ void hmma_loop(
    const __nv_bfloat16* Ah, const __nv_bfloat16* Al,
    const __nv_bfloat16* Bh, const __nv_bfloat16* Bl,
    int ldA, int ldB, char* smbase, float (&c)[2][8][4])
{
    const int tid = threadIdx.x, lane = tid & 31, wid = tid >> 5;
    const int wm = (wid & 3) * 32, wn = (wid >> 2) * 64;
    const int rowA = (lane & 7) + ((lane >> 3) & 1) * 8;
    const int colA = (lane >> 4) * 16;
    const int rowB = (lane & 7) + (lane >> 4) * 8;
    const int colB = ((lane >> 3) & 1) * 16;
    const u32 sb = smem_u32(smbase);
    constexpr int NC = K / 32;

#pragma unroll
    for (int i = 0; i < 2; i++)
#pragma unroll
        for (int j = 0; j < 8; j++)
#pragma unroll
            for (int q = 0; q < 4; q++) c[i][j][q] = 0.0f;

    gemm_issue(sb, Ah, Al, Bh, Bl, ldA, ldB, 0, tid);
    CP_COMMIT();
    for (int ch = 0; ch < NC; ch++) {
        if (ch + 1 < NC) {
            gemm_issue(sb + ((ch + 1) & 1) * GSTG, Ah, Al, Bh, Bl, ldA, ldB, (ch + 1) * 32, tid);
            CP_COMMIT();
            CP_WAIT1();
        } else {
            CP_WAIT0();
        }
        __syncthreads();
        const u32 st = sb + (ch & 1) * GSTG;
#pragma unroll
        for (int kk = 0; kk < 32; kk += 16) {
            u32 ah[2][4], al[2][4], bh[8][2], bl[8][2];
#pragma unroll
            for (int s = 0; s < 2; s++) {
                ldm4(ah[s], st + (wm + s * 16 + rowA) * 80 + kk * 2 + colA);
                ldm4(al[s], st + 10240 + (wm + s * 16 + rowA) * 80 + kk * 2 + colA);
            }
#pragma unroll
            for (int p = 0; p < 4; p++) {
                u32 t4[4];
                ldm4(t4, st + 20480 + (wn + p * 16 + rowB) * 80 + kk * 2 + colB);
                bh[2 * p][0] = t4[0]; bh[2 * p][1] = t4[1];
                bh[2 * p + 1][0] = t4[2]; bh[2 * p + 1][1] = t4[3];
                ldm4(t4, st + 30720 + (wn + p * 16 + rowB) * 80 + kk * 2 + colB);
                bl[2 * p][0] = t4[0]; bl[2 * p][1] = t4[1];
                bl[2 * p + 1][0] = t4[2]; bl[2 * p + 1][1] = t4[3];
            }
#pragma unroll
            for (int i = 0; i < 2; i++)
#pragma unroll
                for (int j = 0; j < 8; j++) {
                    mma16816(c[i][j], ah[i], bh[j]);
                    mma16816(c[i][j], ah[i], bl[j]);
                    mma16816(c[i][j], al[i], bh[j]);
                }
        }
        __syncthreads();
    }
}

// ---------------- misc small kernels ----------------
__global__ void zero_kernel(float* __restrict__ p, int n) {
    int i = blockIdx.x * blockDim.x + threadIdx.x;
    if (i < n) p[i] = 0.0f;
}

__global__ void __launch_bounds__(256) split_kernel(
    const float* __restrict__ s, __nv_bfloat16* __restrict__ dh,
    __nv_bfloat16* __restrict__ dl)
{
    int i = blockIdx.x * 256 + threadIdx.x;
    float4 v = *(const float4*)(s + (size_t)i * 4);
    __nv_bfloat16 h0, h1, h2, h3, l0, l1, l2, l3;
    split2(v.x, h0, l0); split2(v.y, h1, l1);
    split2(v.z, h2, l2); split2(v.w, h3, l3);
    *(uint2*)(dh + (size_t)i * 4) = make_uint2(bfpack(h0, h1), bfpack(h2, h3));
    *(uint2*)(dl + (size_t)i * 4) = make_uint2(bfpack(l0, l1), bfpack(l2, l3));
}

__global__ void __launch_bounds__(256) transpose_split_kernel(
    const float* __restrict__ src, __nv_bfloat16* __restrict__ dh,
    __nv_bfloat16* __restrict__ dl, int R, int C)
{
    __shared__ float t[32][33];
    const int m = blockIdx.z;
    const int c0 = blockIdx.x * 32, r0 = blockIdx.y * 32;
    const int tx = threadIdx.x & 31, ty = threadIdx.x >> 5;
    const float* s = src + (size_t)m * R * C;
#pragma unroll
    for (int j = 0; j < 32; j += 8)
        t[ty + j][tx] = s[(size_t)(r0 + ty + j) * C + c0 + tx];
    __syncthreads();
    const size_t ob = (size_t)m * R * C;
#pragma unroll
    for (int j = 0; j < 32; j += 8) {
        __nv_bfloat16 h, l;
        split2(t[tx][ty + j], h, l);
        dh[ob + (size_t)(c0 + ty + j) * R + r0 + tx] = h;
        dl[ob + (size_t)(c0 + ty + j) * R + r0 + tx] = l;
    }
}

// ---------------- QKV GEMM (HMMA): g_qkv = x @ in_w^T + in_b ----------------
__global__ void __launch_bounds__(256) qkv_hmma(const float* __restrict__ in_b)
{
    extern __shared__ char sm[];
    const int bm = blockIdx.y * 128, bn = blockIdx.x * 128;
    float c[2][8][4];
    hmma_loop<Ddim>(g_xh + (size_t)bm * Ddim, g_xl + (size_t)bm * Ddim,
                    g_iwh + (size_t)bn * Ddim, g_iwl + (size_t)bn * Ddim,
                    Ddim, Ddim, sm, c);
    const int lane = threadIdx.x & 31, wid = threadIdx.x >> 5;
    const int wm = (wid & 3) * 32, wn = (wid >> 2) * 64;
    const int col = bn + wn + (lane & 3) * 2;
#pragma unroll
    for (int i = 0; i < 2; i++) {
        const int m = bm + wm + i * 16 + (lane >> 2);
#pragma unroll
        for (int j = 0; j < 8; j++) {
            float b0 = in_b[col + j * 8], b1 = in_b[col + j * 8 + 1];
            *(float2*)(g_qkv + (size_t)m * QKVW + col + j * 8) =
                make_float2(c[i][j][0] + b0, c[i][j][1] + b1);
            *(float2*)(g_qkv + (size_t)(m + 8) * QKVW + col + j * 8) =
                make_float2(c[i][j][2] + b0, c[i][j][3] + b1);
        }
    }
}

// ---------------- out-proj GEMM (HMMA): g_aout = attn @ out_w^T + out_b -------
__global__ void __launch_bounds__(256) outproj_hmma(const float* __restrict__ out_b)
{
    extern __shared__ char sm[];
    const int bm = blockIdx.y * 128, bn = blockIdx.x * 128;
    float c[2][8][4];
    hmma_loop<Ddim>(g_ah + (size_t)bm * Ddim, g_al + (size_t)bm * Ddim,
                    g_owh + (size_t)bn * Ddim, g_owl + (size_t)bn * Ddim,
                    Ddim, Ddim, sm, c);
    const int lane = threadIdx.x & 31, wid = threadIdx.x >> 5;
    const int wm = (wid & 3) * 32, wn = (wid >> 2) * 64;
    const int col = bn + wn + (lane & 3) * 2;
#pragma unroll
    for (int i = 0; i < 2; i++) {
        const int m = bm + wm + i * 16 + (lane >> 2);
#pragma unroll
        for (int j = 0; j < 8; j++) {
            float b0 = out_b[col + j * 8], b1 = out_b[col + j * 8 + 1];
            *(float2*)(g_aout + (size_t)m * Ddim + col + j * 8) =
                make_float2(c[i][j][0] + b0, c[i][j][1] + b1);
            *(float2*)(g_aout + (size_t)(m + 8) * Ddim + col + j * 8) =
                make_float2(c[i][j][2] + b0, c[i][j][3] + b1);
        }
    }
}

// ---------------- QKV -> bf16 converts ----------------
__global__ void __launch_bounds__(256) qk_convert_kernel()
{
    const int idx = blockIdx.x * 256 + threadIdx.x;
    const int tok = idx >> 7, c4 = (idx & 127) * 4;
    float4 q = *(const float4*)(g_qkv + (size_t)tok * QKVW + c4);
    float4 k = *(const float4*)(g_qkv + (size_t)tok * QKVW + Ddim + c4);
    float qa[4] = {q.x * 0.125f, q.y * 0.125f, q.z * 0.125f, q.w * 0.125f};
    float ka[4] = {k.x, k.y, k.z, k.w};
    __nv_bfloat16 qh[4], ql[4], kh[4], kl[4];
#pragma unroll
    for (int i = 0; i < 4; i++) { split2(qa[i], qh[i], ql[i]); split2(ka[i], kh[i], kl[i]); }
    const size_t o = (size_t)tok * Ddim + c4;
    *(uint2*)(g_qh + o) = make_uint2(bfpack(qh[0], qh[1]), bfpack(qh[2], qh[3]));
    *(uint2*)(g_ql + o) = make_uint2(bfpack(ql[0], ql[1]), bfpack(ql[2], ql[3]));
    *(uint2*)(g_kh + o) = make_uint2(bfpack(kh[0], kh[1]), bfpack(kh[2], kh[3]));
    *(uint2*)(g_kl + o) = make_uint2(bfpack(kl[0], kl[1]), bfpack(kl[2], kl[3]));
}

__global__ void __launch_bounds__(256) v_trans_split_kernel()
{
    __shared__ float t[32][33];
    const int b = blockIdx.z;
    const int s0 = blockIdx.x * 32, d0 = blockIdx.y * 32;
    const int tx = threadIdx.x & 31, ty = threadIdx.x >> 5;
#pragma unroll
    for (int j = 0; j < 32; j += 8)
        t[ty + j][tx] = g_qkv[(size_t)(b * Sdim + s0 + ty + j) * QKVW + 2 * Ddim + d0 + tx];
    __syncthreads();
#pragma unroll
    for (int j = 0; j < 32; j += 8) {
        __nv_bfloat16 h, l;
        split2(t[tx][ty + j], h, l);
        const size_t o = ((size_t)(b * Ddim + d0 + ty + j)) * Sdim + s0 + tx;
        g_vth[o] = h;
        g_vtl[o] = l;
    }
}

// ================= HMMA flash attention (BQ=64, BK=64, 128 thr) =================
#define FA_STG 36864
#define FA_QOF 73728
#define FA_SMEM 92160

__device__ __forceinline__ void fa_issue(u32 st, int b, int h, int kt, int tid)
{
    int idx = tid;
#pragma unroll
    for (int t = 0; t < 16; t++, idx += 128) {
        int sel = idx >> 9;
        int q = idx & 511;
        int r = q >> 3, kq = q & 7;
        const __nv_bfloat16* src;
        if (sel == 0)      src = g_kh  + (size_t)(b * Sdim + kt * 64 + r) * Ddim + h * HD + kq * 8;
        else if (sel == 1) src = g_kl  + (size_t)(b * Sdim + kt * 64 + r) * Ddim + h * HD + kq * 8;
        else if (sel == 2) src = g_vth + ((size_t)(b * Ddim + h * HD + r)) * Sdim + kt * 64 + kq * 8;
        else               src = g_vtl + ((size_t)(b * Ddim + h * HD + r)) * Sdim + kt * 64 + kq * 8;
        cp16(st + sel * 9216 + r * 144 + kq * 16, src);
    }
}

__global__ void __launch_bounds__(128) flash_attn_hmma()
{
    extern __shared__ char sm[];
    const u32 sb = smem_u32(sm);
    const int tid = threadIdx.x, lane = tid & 31, w = tid >> 5;
    const int qt = blockIdx.x, h = blockIdx.y, b = blockIdx.z;
    const int q0 = qt * 64;
    const int rowA = (lane & 7) + ((lane >> 3) & 1) * 8;
    const int colA = (lane >> 4) * 16;
    const int rowB = (lane & 7) + (lane >> 4) * 8;
    const int colB = ((lane >> 3) & 1) * 16;

    {
        int idx = tid;
#pragma unroll
        for (int t = 0; t < 8; t++, idx += 128) {
            int sel = idx >> 9, q = idx & 511;
            int r = q >> 3, kq = q & 7;
            const __nv_bfloat16* src = (sel ? g_ql : g_qh)
                + (size_t)(b * Sdim + q0 + r) * Ddim + h * HD + kq * 8;
            cp16(sb + FA_QOF + sel * 9216 + r * 144 + kq * 16, src);
        }
        CP_COMMIT();
    }
    fa_issue(sb, b, h, 0, tid);
    CP_COMMIT();
    CP_WAIT1();
    __syncthreads();

    u32 qhf[4][4], qlf[4][4];
#pragma unroll
    for (int kc = 0; kc < 4; kc++) {
        ldm4(qhf[kc], sb + FA_QOF + (w * 16 + rowA) * 144 + kc * 32 + colA);
        ldm4(qlf[kc], sb + FA_QOF + 9216 + (w * 16 + rowA) * 144 + kc * 32 + colA);
    }

    float o[8][4];
#pragma unroll
    for (int j = 0; j < 8; j++)
#pragma unroll
        for (int q = 0; q < 4; q++) o[j][q] = 0.0f;
    float M0 = -1e30f, M1 = -1e30f, L0 = 0.0f, L1 = 0.0f;

    for (int kt = 0; kt < 16; kt++) {
        if (kt + 1 < 16) {
            fa_issue(sb + ((kt + 1) & 1) * FA_STG, b, h, kt + 1, tid);
            CP_COMMIT();
            CP_WAIT1();
        } else {
            CP_WAIT0();
        }
        __syncthreads();
        const u32 st = sb + (kt & 1) * FA_STG;

        float s[8][4];
#pragma unroll
        for (int j = 0; j < 8; j++)
#pragma unroll
            for (int q = 0; q < 4; q++) s[j][q] = 0.0f;
#pragma unroll
        for (int kc = 0; kc < 4; kc++) {
            u32 kb[8][2], klb[8][2];
#pragma unroll
            for (int p = 0; p < 4; p++) {
                u32 t4[4];
                ldm4(t4, st + (p * 16 + rowB) * 144 + kc * 32 + colB);
                kb[2 * p][0] = t4[0]; kb[2 * p][1] = t4[1];
                kb[2 * p + 1][0] = t4[2]; kb[2 * p + 1][1] = t4[3];
                ldm4(t4, st + 9216 + (p * 16 + rowB) * 144 + kc * 32 + colB);
                klb[2 * p][0] = t4[0]; klb[2 * p][1] = t4[1];
                klb[2 * p + 1][0] = t4[2]; klb[2 * p + 1][1] = t4[3];
            }
#pragma unroll
            for (int j = 0; j < 8; j++) {
                mma16816(s[j], qhf[kc], kb[j]);
                mma16816(s[j], qhf[kc], klb[j]);
                mma16816(s[j], qlf[kc], kb[j]);
            }
        }

        float mt0 = -1e30f, mt1 = -1e30f;
#pragma unroll
        for (int j = 0; j < 8; j++) {
            mt0 = fmaxf(mt0, fmaxf(s[j][0], s[j][1]));
            mt1 = fmaxf(mt1, fmaxf(s[j][2], s[j][3]));
        }
        mt0 = fmaxf(mt0, __shfl_xor_sync(0xffffffffu, mt0, 1));
        mt0 = fmaxf(mt0, __shfl_xor_sync(0xffffffffu, mt0, 2));
        mt1 = fmaxf(mt1, __shfl_xor_sync(0xffffffffu, mt1, 1));
        mt1 = fmaxf(mt1, __shfl_xor_sync(0xffffffffu, mt1, 2));
        float nM0 = fmaxf(M0, mt0), nM1 = fmaxf(M1, mt1);
        float a0 = __expf(M0 - nM0), a1 = __expf(M1 - nM1);
        M0 = nM0; M1 = nM1;
        float rs0 = 0.0f, rs1 = 0.0f;
#pragma unroll
        for (int j = 0; j < 8; j++) {
            s[j][0] = __expf(s[j][0] - M0);
            s[j][1] = __expf(s[j][1] - M0);
            s[j][2] = __expf(s[j][2] - M1);
            s[j][3] = __expf(s[j][3] - M1);
            rs0 += s[j][0] + s[j][1];
            rs1 += s[j][2] + s[j][3];
        }
        rs0 += __shfl_xor_sync(0xffffffffu, rs0, 1);
        rs0 += __shfl_xor_sync(0xffffffffu, rs0, 2);
        rs1 += __shfl_xor_sync(0xffffffffu, rs1, 1);
        rs1 += __shfl_xor_sync(0xffffffffu, rs1, 2);
        L0 = a0 * L0 + rs0;
        L1 = a1 * L1 + rs1;
#pragma unroll
        for (int j = 0; j < 8; j++) {
            o[j][0] *= a0; o[j][1] *= a0;
            o[j][2] *= a1; o[j][3] *= a1;
        }

#pragma unroll
        for (int kc = 0; kc < 4; kc++) {
            u32 ph[4], pl[4];
            {
                const float* pA = s[2 * kc];
                const float* pB = s[2 * kc + 1];
                __nv_bfloat16 hh[8], ll[8];
                split2(pA[0], hh[0], ll[0]); split2(pA[1], hh[1], ll[1]);
                split2(pA[2], hh[2], ll[2]); split2(pA[3], hh[3], ll[3]);
                split2(pB[0], hh[4], ll[4]); split2(pB[1], hh[5], ll[5]);
                split2(pB[2], hh[6], ll[6]); split2(pB[3], hh[7], ll[7]);
                ph[0] = bfpack(hh[0], hh[1]); ph[1] = bfpack(hh[2], hh[3]);
                ph[2] = bfpack(hh[4], hh[5]); ph[3] = bfpack(hh[6], hh[7]);
                pl[0] = bfpack(ll[0], ll[1]); pl[1] = bfpack(ll[2], ll[3]);
                pl[2] = bfpack(ll[4], ll[5]); pl[3] = bfpack(ll[6], ll[7]);
            }
            u32 vb[8][2], vlb[8][2];
#pragma unroll
            for (int p = 0; p < 4; p++) {
                u32 t4[4];
                ldm4(t4, st + 18432 + (p * 16 + rowB) * 144 + kc * 32 + colB);
                vb[2 * p][0] = t4[0]; vb[2 * p][1] = t4[1];
                vb[2 * p + 1][0] = t4[2]; vb[2 * p + 1][1] = t4[3];
                ldm4(t4, st + 27648 + (p * 16 + rowB) * 144 + kc * 32 + colB);
                vlb[2 * p][0] = t4[0]; vlb[2 * p][1] = t4[1];
                vlb[2 * p + 1][0] = t4[2]; vlb[2 * p + 1][1] = t4[3];
            }
#pragma unroll
            for (int j = 0; j < 8; j++) {
                mma16816(o[j], ph, vb[j]);
                mma16816(o[j], ph, vlb[j]);
                mma16816(o[j], pl, vb[j]);
            }
        }
        __syncthreads();
    }

    const float i0 = 1.0f / L0, i1 = 1.0f / L1;
    const int m0 = b * Sdim + q0 + w * 16 + (lane >> 2);
    const int dc = h * HD + (lane & 3) * 2;
#pragma unroll
    for (int j = 0; j < 8; j++) {
        __nv_bfloat16 h0, h1, l0, l1;
        split2(o[j][0] * i0, h0, l0); split2(o[j][1] * i0, h1, l1);
        *(u32*)(g_ah + (size_t)m0 * Ddim + dc + j * 8) = bfpack(h0, h1);
        *(u32*)(g_al + (size_t)m0 * Ddim + dc + j * 8) = bfpack(l0, l1);
        split2(o[j][2] * i1, h0, l0); split2(o[j][3] * i1, h1, l1);
        *(u32*)(g_ah + (size_t)(m0 + 8) * Ddim + dc + j * 8) = bfpack(h0, h1);
        *(u32*)(g_al + (size_t)(m0 + 8) * Ddim + dc + j * 8) = bfpack(l0, l1);
    }
}

// ---------------- fused residual add + LayerNorm ----------------
__global__ void __launch_bounds__(128) add_ln_kernel(
    const float* __restrict__ a, const float* __restrict__ r,
    const float* __restrict__ g, const float* __restrict__ be,
    float* __restrict__ out)
{
    const int n = blockIdx.x;
    const int tid = threadIdx.x;
    __shared__ float red[4], red2[4];
    __shared__ float s_mu, s_rstd;
    const float* ap = a + (size_t)n * Ddim;
    const float* rp = r + (size_t)n * Ddim;
    float v[4];
    float sum = 0.0f, sq = 0.0f;
#pragma unroll
    for (int i = 0; i < 4; i++) {
        v[i] = ap[tid + i * 128] + rp[tid + i * 128];
        sum += v[i];
        sq = fmaf(v[i], v[i], sq);
    }
#pragma unroll
    for (int o = 16; o; o >>= 1) {
        sum += __shfl_xor_sync(0xffffffffu, sum, o);
        sq  += __shfl_xor_sync(0xffffffffu, sq, o);
    }
    if ((tid & 31) == 0) { red[tid >> 5] = sum; red2[tid >> 5] = sq; }
    __syncthreads();
    if (tid == 0) {
        float s = red[0] + red[1] + red[2] + red[3];
        float q = red2[0] + red2[1] + red2[2] + red2[3];
        float mu = s * (1.0f / 512.0f);
        s_mu = mu;
        s_rstd = rsqrtf(q * (1.0f / 512.0f) - mu * mu + 1e-5f);
    }
    __syncthreads();
    float mu = s_mu, rstd = s_rstd;
#pragma unroll
    for (int i = 0; i < 4; i++) {
        int d = tid + i * 128;
        out[(size_t)n * Ddim + d] = (v[i] - mu) * rstd * g[d] + be[d];
    }
}

// ---------------- router ----------------
__global__ void __launch_bounds__(256) router_kernel(
    const float* __restrict__ h, const float* __restrict__ rw,
    float* __restrict__ logits_out)
{
    const int w = threadIdx.x >> 5, l = threadIdx.x & 31;
    const int n = blockIdx.x * 8 + w;
    float acc[8];
#pragma unroll
    for (int e = 0; e < 8; e++) acc[e] = 0.0f;
    const float* hp = h + (size_t)n * Ddim;
    for (int d = l; d < Ddim; d += 32) {
        float hv = hp[d];
        const float4* rp = (const float4*)(rw + d * 8);
        float4 r0 = rp[0], r1 = rp[1];
        acc[0] = fmaf(hv, r0.x, acc[0]); acc[1] = fmaf(hv, r0.y, acc[1]);
        acc[2] = fmaf(hv, r0.z, acc[2]); acc[3] = fmaf(hv, r0.w, acc[3]);
        acc[4] = fmaf(hv, r1.x, acc[4]); acc[5] = fmaf(hv, r1.y, acc[5]);
        acc[6] = fmaf(hv, r1.z, acc[6]); acc[7] = fmaf(hv, r1.w, acc[7]);
    }
#pragma unroll
    for (int e = 0; e < 8; e++)
#pragma unroll
        for (int o = 16; o; o >>= 1)
            acc[e] += __shfl_xor_sync(0xffffffffu, acc[e], o);
    if (l == 0) {
        float m = acc[0]; int arg = 0;
#pragma unroll
        for (int e = 1; e < 8; e++) if (acc[e] > m) { m = acc[e]; arg = e; }
        float s = 0.0f;
#pragma unroll
        for (int e = 0; e < 8; e++) s += __expf(acc[e] - m);
#pragma unroll
        for (int e = 0; e < 8; e++) logits_out[(size_t)n * 8 + e] = acc[e];
        g_idx[n] = arg;
        g_pmax[n] = 1.0f / s;
    }
}

// ---------------- capacity scan ----------------
__global__ void __launch_bounds__(256) capacity_kernel(
    const int* __restrict__ capp, float* __restrict__ mask_out)
{
    __shared__ int sidx[Sdim];
    __shared__ float spm[Sdim];
    const int b = blockIdx.x, tid = threadIdx.x;
    for (int s = tid; s < Sdim; s += 256) {
        sidx[s] = g_idx[b * Sdim + s];
        spm[s]  = g_pmax[b * Sdim + s];
    }
    __syncthreads();
    if (tid < Edim) {
        const int e = tid;
        int cap = capp[0];
        if (cap > CAPMAX) cap = CAPMAX;
        int cnt = 0;
        const int base = (b * Edim + e) * CAPMAX;
        for (int s = 0; s < Sdim; s++) {
            if (sidx[s] == e) {
                cnt++;
                if (cnt <= cap) {
                    g_etok[base + cnt - 1] = s;
                    g_escale[base + cnt - 1] = spm[s];
                    mask_out[((size_t)(b * Sdim + s)) * Edim + e] = spm[s];
                }
            }
        }
        g_count[b * Edim + e] = cnt < cap ? cnt : cap;
    }
}

// ---------------- gather h -> packed bf16 hi/lo ----------------
__global__ void __launch_bounds__(256) gather_kernel()
{
    const int tid = threadIdx.x;
    const int row = blockIdx.x * 4 + (tid >> 6);
    const int lane = tid & 63;
    const int combo = row >> 8, slot = row & 255;
    __align__(16) __nv_bfloat16 hb[8], lb[8];
    if (slot < g_count[combo]) {
        const int tok = g_etok[row];
        const int b = combo >> 3;
        const float4* src = (const float4*)(g_h + ((size_t)(b * Sdim + tok)) * Ddim) + lane * 2;
        float4 v0 = src[0], v1 = src[1];
        float v[8] = {v0.x, v0.y, v0.z, v0.w, v1.x, v1.y, v1.z, v1.w};
#pragma unroll
        for (int i = 0; i < 8; i++) split2(v[i], hb[i], lb[i]);
    } else {
#pragma unroll
        for (int i = 0; i < 8; i++) { hb[i] = __float2bfloat16(0.0f); lb[i] = hb[i]; }
    }
    *(uint4*)(g_hgh + (size_t)row * Ddim + lane * 8) = *(uint4*)hb;
    *(uint4*)(g_hgl + (size_t)row * Ddim + lane * 8) = *(uint4*)lb;
}

// ---------------- FFN1: y = gelu(hg @ wi^T), split store ----------------
__global__ void __launch_bounds__(256) ffn1_hmma()
{
    extern __shared__ char sm[];
    const int combo = blockIdx.z;
    const int cnt = g_count[combo];
    const int bm = blockIdx.y * 128;
    if (bm >= cnt) return;
    const int e = combo & 7;
    const int bn = blockIdx.x * 128;
    float c[2][8][4];
    hmma_loop<Ddim>(g_hgh + (size_t)(combo * CAPMAX + bm) * Ddim,
                    g_hgl + (size_t)(combo * CAPMAX + bm) * Ddim,
                    g_w1h + ((size_t)e * Fdim + bn) * Ddim,
                    g_w1l + ((size_t)e * Fdim + bn) * Ddim,
                    Ddim, Ddim, sm, c);
    const int lane = threadIdx.x & 31, wid = threadIdx.x >> 5;
    const int wm = (wid & 3) * 32, wn = (wid >> 2) * 64;
    const int col = bn + wn + (lane & 3) * 2;
#pragma unroll
    for (int i = 0; i < 2; i++) {
        const size_t m = combo * CAPMAX + bm + wm + i * 16 + (lane >> 2);
#pragma unroll
        for (int j = 0; j < 8; j++) {
            __nv_bfloat16 h0, h1, l0, l1;
            split2(gelu_exact(c[i][j][0]), h0, l0);
            split2(gelu_exact(c[i][j][1]), h1, l1);
            *(u32*)(g_ygh + m * Fdim + col + j * 8) = bfpack(h0, h1);
            *(u32*)(g_ygl + m * Fdim + col + j * 8) = bfpack(l0, l1);
            split2(gelu_exact(c[i][j][2]), h0, l0);
            split2(gelu_exact(c[i][j][3]), h1, l1);
            *(u32*)(g_ygh + (m + 8) * Fdim + col + j * 8) = bfpack(h0, h1);
            *(u32*)(g_ygl + (m + 8) * Fdim + col + j * 8) = bfpack(l0, l1);
        }
    }
}

// ---------------- FFN2: scatter((y @ wo^T) * scale) ----------------
__global__ void __launch_bounds__(256) ffn2_hmma()
{
    extern __shared__ char sm[];
    const int combo = blockIdx.z;
    const int cnt = g_count[combo];
    const int bm = blockIdx.y * 128;
    if (bm >= cnt) return;
    const int e = combo & 7;
    const int b = combo >> 3;
    const int bn = blockIdx.x * 128;
    float c[2][8][4];
    hmma_loop<Fdim>(g_ygh + (size_t)(combo * CAPMAX + bm) * Fdim,
                    g_ygl + (size_t)(combo * CAPMAX + bm) * Fdim,
                    g_w2h + ((size_t)e * Ddim + bn) * Fdim,
                    g_w2l + ((size_t)e * Ddim + bn) * Fdim,
                    Fdim, Fdim, sm, c);
    const int lane = threadIdx.x & 31, wid = threadIdx.x >> 5;
    const int wm = (wid & 3) * 32, wn = (wid >> 2) * 64;
    const int col = bn + wn + (lane & 3) * 2;
#pragma unroll
    for (int i = 0; i < 2; i++) {
        const int m0 = bm + wm + i * 16 + (lane >> 2);
#pragma unroll
        for (int half = 0; half < 2; half++) {
            const int m = m0 + half * 8;
            if (m < cnt) {
                const int tok = g_etok[combo * CAPMAX + m];
                const float sc = g_escale[combo * CAPMAX + m];
                float* op = g_moe + ((size_t)(b * Sdim + tok)) * Ddim + col;
#pragma unroll
                for (int j = 0; j < 8; j++)
                    *(float2*)(op + j * 8) =
                        make_float2(sc * c[i][j][half * 2], sc * c[i][j][half * 2 + 1]);
            }
        }
    }
}

// ---------------- launch ----------------
extern "C" void kernel_launch(void* const* d_in, const int* in_sizes, int n_in,
                              void* d_out, int out_size)
{
    const float* x     = (const float*)d_in[0];
    const float* in_w  = (const float*)d_in[1];
    const float* in_b  = (const float*)d_in[2];
    const float* out_w = (const float*)d_in[3];
    const float* out_b = (const float*)d_in[4];
    const float* ln1g  = (const float*)d_in[5];
    const float* ln1b  = (const float*)d_in[6];
    const float* ln2g  = (const float*)d_in[7];
    const float* ln2b  = (const float*)d_in[8];
    const float* rw    = (const float*)d_in[9];
    const float* wi    = (const float*)d_in[10];
    const float* wo    = (const float*)d_in[11];
    const int*   cap   = (const int*)d_in[12];

    float* out        = (float*)d_out;
    float* logits_out = out + (size_t)NTOK * Ddim;
    float* mask_out   = logits_out + (size_t)NTOK * Edim;

    float *p_aout, *p_h, *p_moe;
    __nv_bfloat16 *p_xh, *p_xl, *p_iwh, *p_iwl, *p_owh, *p_owl, *p_w1h, *p_w1l, *p_w2h, *p_w2l;
    cudaGetSymbolAddress((void**)&p_aout, g_aout);
    cudaGetSymbolAddress((void**)&p_h,    g_h);
    cudaGetSymbolAddress((void**)&p_moe,  g_moe);
    cudaGetSymbolAddress((void**)&p_xh,   g_xh);
    cudaGetSymbolAddress((void**)&p_xl,   g_xl);
    cudaGetSymbolAddress((void**)&p_iwh,  g_iwh);
    cudaGetSymbolAddress((void**)&p_iwl,  g_iwl);
    cudaGetSymbolAddress((void**)&p_owh,  g_owh);
    cudaGetSymbolAddress((void**)&p_owl,  g_owl);
    cudaGetSymbolAddress((void**)&p_w1h,  g_w1h);
    cudaGetSymbolAddress((void**)&p_w1l,  g_w1l);
    cudaGetSymbolAddress((void**)&p_w2h,  g_w2h);
    cudaGetSymbolAddress((void**)&p_w2l,  g_w2l);

    cudaFuncSetAttribute(qkv_hmma,    cudaFuncAttributeMaxDynamicSharedMemorySize, GEMM_SMEM);
    cudaFuncSetAttribute(outproj_hmma, cudaFuncAttributeMaxDynamicSharedMemorySize, GEMM_SMEM);
    cudaFuncSetAttribute(ffn1_hmma,   cudaFuncAttributeMaxDynamicSharedMemorySize, GEMM_SMEM);
    cudaFuncSetAttribute(ffn2_hmma,   cudaFuncAttributeMaxDynamicSharedMemorySize, GEMM_SMEM);
    cudaFuncSetAttribute(flash_attn_hmma, cudaFuncAttributeMaxDynamicSharedMemorySize, FA_SMEM);

    // 0) splits (weights + input)
    split_kernel<<<NTOK * Ddim / 1024, 256>>>(x, p_xh, p_xl);
    split_kernel<<<QKVW * Ddim / 1024, 256>>>(in_w, p_iwh, p_iwl);
    split_kernel<<<Ddim * Ddim / 1024, 256>>>(out_w, p_owh, p_owl);
    transpose_split_kernel<<<dim3(Fdim / 32, Ddim / 32, Edim), 256>>>(wi, p_w1h, p_w1l, Ddim, Fdim);
    transpose_split_kernel<<<dim3(Ddim / 32, Fdim / 32, Edim), 256>>>(wo, p_w2h, p_w2l, Fdim, Ddim);

    // 1) QKV projection (HMMA)
    qkv_hmma<<<dim3(QKVW / 128, NTOK / 128), 256, GEMM_SMEM>>>(in_b);

    // 2) converts for attention
    qk_convert_kernel<<<NTOK * 128 / 256, 256>>>();
    v_trans_split_kernel<<<dim3(Sdim / 32, Ddim / 32, Bdim), 256>>>();

    // 3) flash attention (HMMA)
    flash_attn_hmma<<<dim3(Sdim / 64, Hdim, Bdim), 128, FA_SMEM>>>();

    // 4) out-proj (HMMA) + LN1
    outproj_hmma<<<dim3(Ddim / 128, NTOK / 128), 256, GEMM_SMEM>>>(out_b);
    add_ln_kernel<<<NTOK, 128>>>(p_aout, x, ln1g, ln1b, p_h);

    // 5) zero + router + dispatch
    zero_kernel<<<(NTOK * Ddim + 255) / 256, 256>>>(p_moe, NTOK * Ddim);
    zero_kernel<<<(NTOK * Edim + 255) / 256, 256>>>(mask_out, NTOK * Edim);
    router_kernel<<<NTOK / 8, 256>>>(p_h, rw, logits_out);
    capacity_kernel<<<Bdim, 256>>>(cap, mask_out);
    gather_kernel<<<(32 * CAPMAX) / 4, 256>>>();

    // 6) expert FFN (HMMA)
    ffn1_hmma<<<dim3(Fdim / 128, CAPMAX / 128, 32), 256, GEMM_SMEM>>>();
    ffn2_hmma<<<dim3(Ddim / 128, CAPMAX / 128, 32), 256, GEMM_SMEM>>>();

    // 7) out = LN2(h + moe)
    add_ln_kernel<<<NTOK, 128>>>(p_moe, p_h, ln2g, ln2b, out);
}